// round 3
// baseline (speedup 1.0000x reference)
#include <cuda_runtime.h>
#include <math.h>

#define HIDDEN 256
#define SEQ    233
#define BATCH  1024
#define MROWS  (BATCH * SEQ)          // 238592 = 128 * 1864
#define SCALE  0.0625f                // 1/sqrt(256)
#define NEG    (-10000.0f)

// Scratch: S = [M, 1024] fp32: cols [0,256)=s0, [256,512)=s1, [512,768)=s2, [768,1024)=s3
static __device__ float g_S[(size_t)MROWS * 1024];

// ---------------------------------------------------------------------------
// Kernel A: S[m, 256*w + o] = sum_h X[m,h] * W_w[o,h] + b_w[o]
// Tiled fp32 GEMM: BM=128, BN=128, BK=8, 256 threads, 8x8 micro-tile,
// double-buffered SMEM, k-major SMEM layout, conflict-free LDS.128.
// ---------------------------------------------------------------------------
__global__ void __launch_bounds__(256, 2) proj_kernel(
    const float* __restrict__ X,
    const float* __restrict__ W0, const float* __restrict__ B0,
    const float* __restrict__ W1, const float* __restrict__ B1,
    const float* __restrict__ W2, const float* __restrict__ B2,
    const float* __restrict__ W3, const float* __restrict__ B3)
{
    __shared__ float As[2][8][128];
    __shared__ float Bs[2][8][128];

    const int tid = threadIdx.x;
    const int tx  = tid & 15;          // n-direction (16)
    const int ty  = tid >> 4;          // m-direction (16)
    const int m0  = blockIdx.y * 128;
    const int n0  = blockIdx.x * 128;

    const int wsel = n0 >> 8;
    const float* W   = (wsel == 0) ? W0 : (wsel == 1) ? W1 : (wsel == 2) ? W2 : W3;
    const float* bia = (wsel == 0) ? B0 : (wsel == 1) ? B1 : (wsel == 2) ? B2 : B3;
    const int nloc0 = n0 & 255;

    // global-load mapping: 128 rows x 8 cols per tile, 2 lanes per row (float4 each)
    const int lrow = tid >> 1;         // 0..127
    const int lk   = (tid & 1) * 4;    // 0 or 4

    const float* Ap = X + (size_t)(m0 + lrow) * HIDDEN + lk;
    const float* Bp = W + (size_t)(nloc0 + lrow) * HIDDEN + lk;

    float4 ra = *(const float4*)Ap;
    float4 rb = *(const float4*)Bp;

    float acc[8][8];
#pragma unroll
    for (int i = 0; i < 8; ++i)
#pragma unroll
        for (int j = 0; j < 8; ++j) acc[i][j] = 0.0f;

    As[0][lk + 0][lrow] = ra.x; As[0][lk + 1][lrow] = ra.y;
    As[0][lk + 2][lrow] = ra.z; As[0][lk + 3][lrow] = ra.w;
    Bs[0][lk + 0][lrow] = rb.x; Bs[0][lk + 1][lrow] = rb.y;
    Bs[0][lk + 2][lrow] = rb.z; Bs[0][lk + 3][lrow] = rb.w;
    __syncthreads();

#pragma unroll 1
    for (int kt = 0; kt < 32; ++kt) {           // 256 / 8
        const int cur = kt & 1;
        if (kt < 31) {
            ra = *(const float4*)(Ap + (kt + 1) * 8);
            rb = *(const float4*)(Bp + (kt + 1) * 8);
        }
#pragma unroll
        for (int k = 0; k < 8; ++k) {
            const float4 a0 = *(const float4*)&As[cur][k][ty * 4];
            const float4 a1 = *(const float4*)&As[cur][k][64 + ty * 4];
            const float4 b0 = *(const float4*)&Bs[cur][k][tx * 4];
            const float4 b1 = *(const float4*)&Bs[cur][k][64 + tx * 4];
            const float av[8] = {a0.x, a0.y, a0.z, a0.w, a1.x, a1.y, a1.z, a1.w};
            const float bv[8] = {b0.x, b0.y, b0.z, b0.w, b1.x, b1.y, b1.z, b1.w};
#pragma unroll
            for (int i = 0; i < 8; ++i)
#pragma unroll
                for (int j = 0; j < 8; ++j)
                    acc[i][j] = fmaf(av[i], bv[j], acc[i][j]);
        }
        if (kt < 31) {
            const int nxt = cur ^ 1;
            As[nxt][lk + 0][lrow] = ra.x; As[nxt][lk + 1][lrow] = ra.y;
            As[nxt][lk + 2][lrow] = ra.z; As[nxt][lk + 3][lrow] = ra.w;
            Bs[nxt][lk + 0][lrow] = rb.x; Bs[nxt][lk + 1][lrow] = rb.y;
            Bs[nxt][lk + 2][lrow] = rb.z; Bs[nxt][lk + 3][lrow] = rb.w;
            __syncthreads();
        }
    }

    float bv0[4], bv1[4];
#pragma unroll
    for (int j = 0; j < 4; ++j) {
        bv0[j] = bia[nloc0 + tx * 4 + j];
        bv1[j] = bia[nloc0 + 64 + tx * 4 + j];
    }
#pragma unroll
    for (int i = 0; i < 8; ++i) {
        const int mr = (i < 4) ? (ty * 4 + i) : (64 + ty * 4 + (i - 4));
        float4 o0, o1;
        o0.x = acc[i][0] + bv0[0]; o0.y = acc[i][1] + bv0[1];
        o0.z = acc[i][2] + bv0[2]; o0.w = acc[i][3] + bv0[3];
        o1.x = acc[i][4] + bv1[0]; o1.y = acc[i][5] + bv1[1];
        o1.z = acc[i][6] + bv1[2]; o1.w = acc[i][7] + bv1[3];
        float* outp = &g_S[(size_t)(m0 + mr) * 1024 + n0];
        *(float4*)(outp + tx * 4)      = o0;
        *(float4*)(outp + 64 + tx * 4) = o1;
    }
}

// ---------------------------------------------------------------------------
// Kernel B: per (batch, segment) attention.
//   scores = s1 @ s2^T * SCALE + diag(NEG); probs = softmax(scores)
//   out = s0 - probs @ s3
// SMEM: sKT [256][128] (s2^T, XOR-swizzled, pass1; aliased as sV [n][256] pass2)
//       probs [128][128]
//       s1T [256][32] (chunk of s1^T, XOR-swizzled)
// ---------------------------------------------------------------------------
#define ATTN_SMEM_FLOATS (256 * 128 + 128 * 128 + 256 * 32)   // 57344
#define ATTN_SMEM_BYTES  (ATTN_SMEM_FLOATS * 4)               // 229376

__global__ void __launch_bounds__(256, 1) attn_kernel(float* __restrict__ out)
{
    extern __shared__ float sm[];
    float* sKT   = sm;                              // [256][128] pass1 / sV [n][256] pass2
    float* probs = sm + 256 * 128;                  // [128][128]
    float* s1T   = sm + 256 * 128 + 128 * 128;      // [256][32]

    const int seg = blockIdx.x;
    const int b   = blockIdx.y;
    const int n   = (seg == 0) ? 103 : (seg == 1) ? 119 : 11;
    const int off = (seg == 0) ? 0   : (seg == 1) ? 103 : 222;

    const size_t rowbase = ((size_t)b * SEQ + off) * 1024;
    const int tid = threadIdx.x;

    // ---- fill sKT = s2^T (k-major), XOR swizzle on column-group, zero pad j>=n
    for (int slot = tid; slot < 128 * 64; slot += 256) {
        const int j  = slot >> 6;
        const int kv = slot & 63;
        float4 v = make_float4(0.f, 0.f, 0.f, 0.f);
        if (j < n) v = *(const float4*)&g_S[rowbase + (size_t)j * 1024 + 512 + kv * 4];
        const int col = (((j >> 2) ^ (kv & 7)) << 2) + (j & 3);
        const int k0  = kv * 4;
        sKT[(k0 + 0) * 128 + col] = v.x;
        sKT[(k0 + 1) * 128 + col] = v.y;
        sKT[(k0 + 2) * 128 + col] = v.z;
        sKT[(k0 + 3) * 128 + col] = v.w;
    }
    __syncthreads();

    const int jx  = tid & 31;   // pass1: 32 threads over j (x4 each -> 128)
    const int iy  = tid >> 5;   // pass1: 8 threads over i (x4 each -> 32)
    const int nch = (n + 31) >> 5;

    // ================= pass 1: scores + softmax, 32-row chunks =================
    for (int ch = 0; ch < nch; ++ch) {
        const int i0 = ch << 5;

        // fill s1T (rows i0..i0+31 transposed, swizzled; zero for i>=n)
        for (int slot = tid; slot < 32 * 64; slot += 256) {
            const int il = slot >> 6;
            const int kv = slot & 63;
            const int gi = i0 + il;
            float4 v = make_float4(0.f, 0.f, 0.f, 0.f);
            if (gi < n) v = *(const float4*)&g_S[rowbase + (size_t)gi * 1024 + 256 + kv * 4];
            const int col = (((il >> 2) ^ (kv & 7)) << 2) + (il & 3);
            const int k0  = kv * 4;
            s1T[(k0 + 0) * 32 + col] = v.x;
            s1T[(k0 + 1) * 32 + col] = v.y;
            s1T[(k0 + 2) * 32 + col] = v.z;
            s1T[(k0 + 3) * 32 + col] = v.w;
        }
        __syncthreads();

        float accS[4][4];
#pragma unroll
        for (int i = 0; i < 4; ++i)
#pragma unroll
            for (int j = 0; j < 4; ++j) accS[i][j] = 0.0f;

#pragma unroll 8
        for (int k = 0; k < 256; ++k) {
            const int f = (k >> 2) & 7;
            const float4 a = *(const float4*)(s1T + k * 32  + (((iy ^ f)) << 2));
            const float4 q = *(const float4*)(sKT + k * 128 + (((jx ^ f)) << 2));
            const float a4[4] = {a.x, a.y, a.z, a.w};
            const float q4[4] = {q.x, q.y, q.z, q.w};
#pragma unroll
            for (int i = 0; i < 4; ++i)
#pragma unroll
                for (int j = 0; j < 4; ++j)
                    accS[i][j] = fmaf(a4[i], q4[j], accS[i][j]);
        }

        // scale + diagonal mask, write raw scores into probs
#pragma unroll
        for (int ii = 0; ii < 4; ++ii) {
            const int gi = i0 + iy * 4 + ii;
            float4 p;
            p.x = accS[ii][0] * SCALE + ((gi == jx * 4 + 0) ? NEG : 0.f);
            p.y = accS[ii][1] * SCALE + ((gi == jx * 4 + 1) ? NEG : 0.f);
            p.z = accS[ii][2] * SCALE + ((gi == jx * 4 + 2) ? NEG : 0.f);
            p.w = accS[ii][3] * SCALE + ((gi == jx * 4 + 3) ? NEG : 0.f);
            *(float4*)&probs[gi * 128 + jx * 4] = p;
        }
        __syncthreads();

        // softmax over valid rows of this chunk: 8 warps x 4 rows
        {
            const int lane = tid & 31;
            const int w    = tid >> 5;
#pragma unroll
            for (int r = 0; r < 4; ++r) {
                const int gi = i0 + w * 4 + r;
                if (gi >= n) break;                 // uniform per warp
                float mx = -1e30f;
                for (int j = lane; j < n; j += 32)
                    mx = fmaxf(mx, probs[gi * 128 + j]);
#pragma unroll
                for (int o = 16; o; o >>= 1)
                    mx = fmaxf(mx, __shfl_xor_sync(0xffffffffu, mx, o));
                float ssum = 0.f;
                for (int j = lane; j < n; j += 32) {
                    const float e = __expf(probs[gi * 128 + j] - mx);
                    probs[gi * 128 + j] = e;
                    ssum += e;
                }
#pragma unroll
                for (int o = 16; o; o >>= 1)
                    ssum += __shfl_xor_sync(0xffffffffu, ssum, o);
                const float inv = 1.0f / ssum;
                for (int j = lane; j < n; j += 32)
                    probs[gi * 128 + j] *= inv;
            }
        }
        __syncthreads();
    }

    // ================= pass 2: out = s0 - probs @ s3 =================
    // repurpose sKT region as sV[j][256] (row-major, no transpose needed)
    for (int slot = tid; slot < n * 64; slot += 256) {
        const int j  = slot >> 6;
        const int kv = slot & 63;
        *(float4*)&sm[j * 256 + kv * 4] =
            *(const float4*)&g_S[rowbase + (size_t)j * 1024 + 768 + kv * 4];
    }
    __syncthreads();

    const int tx = tid & 31;   // 32 threads over h (x8 each, split 2 float4 halves)
    const int ty = tid >> 5;   // 8 threads over i (x4 each -> 32)

    for (int ch = 0; ch < nch; ++ch) {
        const int i0 = ch << 5;
        const int ib = i0 + ty * 4;

        float acc[4][8];
#pragma unroll
        for (int i = 0; i < 4; ++i)
#pragma unroll
            for (int h = 0; h < 8; ++h) acc[i][h] = 0.0f;

        for (int j = 0; j < n; ++j) {
            const float4 v0 = *(const float4*)&sm[j * 256 + tx * 4];
            const float4 v1 = *(const float4*)&sm[j * 256 + 128 + tx * 4];
            const float p[4] = {probs[(ib + 0) * 128 + j],
                                probs[(ib + 1) * 128 + j],
                                probs[(ib + 2) * 128 + j],
                                probs[(ib + 3) * 128 + j]};
            const float v[8] = {v0.x, v0.y, v0.z, v0.w, v1.x, v1.y, v1.z, v1.w};
#pragma unroll
            for (int i = 0; i < 4; ++i)
#pragma unroll
                for (int h = 0; h < 8; ++h)
                    acc[i][h] = fmaf(p[i], v[h], acc[i][h]);
        }

#pragma unroll
        for (int ii = 0; ii < 4; ++ii) {
            const int gi = ib + ii;
            if (gi < n) {
                const float4 a0 = *(const float4*)&g_S[rowbase + (size_t)gi * 1024 + tx * 4];
                const float4 a1 = *(const float4*)&g_S[rowbase + (size_t)gi * 1024 + 128 + tx * 4];
                float4 o0, o1;
                o0.x = a0.x - acc[ii][0]; o0.y = a0.y - acc[ii][1];
                o0.z = a0.z - acc[ii][2]; o0.w = a0.w - acc[ii][3];
                o1.x = a1.x - acc[ii][4]; o1.y = a1.y - acc[ii][5];
                o1.z = a1.z - acc[ii][6]; o1.w = a1.w - acc[ii][7];
                const size_t ob = ((size_t)b * SEQ + off + gi) * 256;
                *(float4*)&out[ob + tx * 4]       = o0;
                *(float4*)&out[ob + 128 + tx * 4] = o1;
            }
        }
    }
}

// ---------------------------------------------------------------------------
extern "C" void kernel_launch(void* const* d_in, const int* in_sizes, int n_in,
                              void* d_out, int out_size)
{
    const float* toks = (const float*)d_in[0];
    const float* W0   = (const float*)d_in[1];
    const float* b0   = (const float*)d_in[2];
    const float* W1   = (const float*)d_in[3];
    const float* b1   = (const float*)d_in[4];
    const float* W2   = (const float*)d_in[5];
    const float* b2   = (const float*)d_in[6];
    const float* W3   = (const float*)d_in[7];
    const float* b3   = (const float*)d_in[8];
    float* out = (float*)d_out;

    // Projections: S = X @ [W0;W1;W2;W3]^T + b  -> g_S [238592, 1024]
    dim3 gA(1024 / 128, MROWS / 128);   // (8, 1864)
    proj_kernel<<<gA, 256>>>(toks, W0, b0, W1, b1, W2, b2, W3, b3);

    // Attention per (segment, batch)
    cudaFuncSetAttribute(attn_kernel,
                         cudaFuncAttributeMaxDynamicSharedMemorySize,
                         ATTN_SMEM_BYTES);
    dim3 gB(3, BATCH);
    attn_kernel<<<gB, 256, ATTN_SMEM_BYTES>>>(out);
}

// round 5
// speedup vs baseline: 1.4976x; 1.4976x over previous
#include <cuda_runtime.h>
#include <cuda_bf16.h>
#include <cstdint>
#include <math.h>

#define HIDDEN 256
#define SEQ    233
#define BATCH  1024
#define MROWS  (BATCH * SEQ)          // 238592 = 128 * 1864
#define SCALE  0.0625f                // 1/sqrt(256)
#define NEG    (-10000.0f)

// Scratch: S = [M, 1024] fp32: cols [0,256)=s0, [256,512)=s1, [512,768)=s2, [768,1024)=s3
static __device__ float g_S[(size_t)MROWS * 1024];

__device__ __forceinline__ uint32_t smem_u32(const void* p) {
    uint32_t a;
    asm("{ .reg .u64 t; cvta.to.shared.u64 t, %1; cvt.u32.u64 %0, t; }" : "=r"(a) : "l"(p));
    return a;
}
__device__ __forceinline__ uint32_t b2u(__nv_bfloat162 h) {
    return *reinterpret_cast<uint32_t*>(&h);
}
__device__ __forceinline__ void ldmatrix_x4(uint32_t* r, uint32_t addr) {
    asm volatile("ldmatrix.sync.aligned.m8n8.x4.shared.b16 {%0,%1,%2,%3}, [%4];"
                 : "=r"(r[0]), "=r"(r[1]), "=r"(r[2]), "=r"(r[3]) : "r"(addr));
}
__device__ __forceinline__ void mma_bf16(float* c, const uint32_t* a, const uint32_t* b) {
    asm volatile(
        "mma.sync.aligned.m16n8k16.row.col.f32.bf16.bf16.f32 "
        "{%0,%1,%2,%3}, {%4,%5,%6,%7}, {%8,%9}, {%0,%1,%2,%3};"
        : "+f"(c[0]), "+f"(c[1]), "+f"(c[2]), "+f"(c[3])
        : "r"(a[0]), "r"(a[1]), "r"(a[2]), "r"(a[3]), "r"(b[0]), "r"(b[1]));
}
// split fp32x8 -> hi/lo bf16x8 (two uint4 SMEM stores)
__device__ __forceinline__ void split8(const float4 v0, const float4 v1,
                                       uint4& hi, uint4& lo) {
    __nv_bfloat162 h0 = __floats2bfloat162_rn(v0.x, v0.y);
    __nv_bfloat162 h1 = __floats2bfloat162_rn(v0.z, v0.w);
    __nv_bfloat162 h2 = __floats2bfloat162_rn(v1.x, v1.y);
    __nv_bfloat162 h3 = __floats2bfloat162_rn(v1.z, v1.w);
    float2 f0 = __bfloat1622float2(h0), f1 = __bfloat1622float2(h1);
    float2 f2 = __bfloat1622float2(h2), f3 = __bfloat1622float2(h3);
    __nv_bfloat162 l0 = __floats2bfloat162_rn(v0.x - f0.x, v0.y - f0.y);
    __nv_bfloat162 l1 = __floats2bfloat162_rn(v0.z - f1.x, v0.w - f1.y);
    __nv_bfloat162 l2 = __floats2bfloat162_rn(v1.x - f2.x, v1.y - f2.y);
    __nv_bfloat162 l3 = __floats2bfloat162_rn(v1.z - f3.x, v1.w - f3.y);
    hi = make_uint4(b2u(h0), b2u(h1), b2u(h2), b2u(h3));
    lo = make_uint4(b2u(l0), b2u(l1), b2u(l2), b2u(l3));
}

// ===========================================================================
// Kernel A (mma.sync bf16 hi/lo): S[m, 256*wsel + o] = X[m,:] . W[o,:] + b[o]
// CTA: 128x128 tile, BK=128, 2 K-chunks. SMEM: Ahi/Alo/Bhi/Blo 32KB each,
// [row][128] bf16 rows of 16 groups x 16B, group XOR-swizzled by (row & 7).
// ===========================================================================
#define PJ_SMEM 131072

__global__ void __launch_bounds__(256, 1) proj_mma_kernel(
    const float* __restrict__ X,
    const float* __restrict__ W0, const float* __restrict__ B0,
    const float* __restrict__ W1, const float* __restrict__ B1,
    const float* __restrict__ W2, const float* __restrict__ B2,
    const float* __restrict__ W3, const float* __restrict__ B3)
{
    extern __shared__ __align__(16) char smp[];
    const uint32_t sAhi = smem_u32(smp);
    const uint32_t sAlo = sAhi + 32768;
    const uint32_t sBhi = sAhi + 65536;
    const uint32_t sBlo = sAhi + 98304;

    const int tid  = threadIdx.x;
    const int wid  = tid >> 5;
    const int lane = tid & 31;
    const int wm   = wid & 3;          // warp m-block (32 rows each)
    const int wn   = wid >> 2;         // warp n-block (64 cols each)

    const int bx = blockIdx.x;         // 0..7 : 128-col slab of the 1024 cols
    const int m0 = blockIdx.y * 128;
    const int wsel = bx >> 1;
    const float* W   = (wsel == 0) ? W0 : (wsel == 1) ? W1 : (wsel == 2) ? W2 : W3;
    const float* bia = (wsel == 0) ? B0 : (wsel == 1) ? B1 : (wsel == 2) ? B2 : B3;
    const int nloc0 = (bx & 1) * 128;  // row offset inside W

    float acc[2][8][4];
#pragma unroll
    for (int i = 0; i < 2; ++i)
#pragma unroll
        for (int j = 0; j < 8; ++j)
#pragma unroll
            for (int q = 0; q < 4; ++q) acc[i][j][q] = 0.0f;

    // ldmatrix per-lane source addresses (offsets within a tile buffer)
    // A: matrices (rows 0-7 kG0),(rows 8-15 kG0),(rows 0-7 kG1),(rows 8-15 kG1)
    const int a_row = lane & 15;
    const int a_gh  = lane >> 4;            // 0/1 -> +0 / +8 k
    // B pair: (n0-7 kG0),(n0-7 kG1),(n8-15 kG0),(n8-15 kG1)
    const int b_nof = (lane & 7) + ((lane & 16) ? 8 : 0);
    const int b_gh  = (lane >> 3) & 1;

#pragma unroll 1
    for (int c = 0; c < 2; ++c) {
        if (c) __syncthreads();

        // ---- load + split chunk c: A[128][128], B[128][128]
#pragma unroll
        for (int it = 0; it < 8; ++it) {
            const int gi  = tid + it * 256;      // 0..2047
            const int row = gi >> 4;
            const int g   = gi & 15;
            const float* src = X + (size_t)(m0 + row) * HIDDEN + c * 128 + g * 8;
            uint4 hi, lo;
            split8(__ldg((const float4*)src), __ldg((const float4*)(src + 4)), hi, lo);
            const uint32_t off = row * 256 + ((g ^ (row & 7)) << 4);
            *(uint4*)(smp + off)         = hi;
            *(uint4*)(smp + 32768 + off) = lo;
        }
#pragma unroll
        for (int it = 0; it < 8; ++it) {
            const int gi  = tid + it * 256;
            const int row = gi >> 4;
            const int g   = gi & 15;
            const float* src = W + (size_t)(nloc0 + row) * HIDDEN + c * 128 + g * 8;
            uint4 hi, lo;
            split8(__ldg((const float4*)src), __ldg((const float4*)(src + 4)), hi, lo);
            const uint32_t off = row * 256 + ((g ^ (row & 7)) << 4);
            *(uint4*)(smp + 65536 + off) = hi;
            *(uint4*)(smp + 98304 + off) = lo;
        }
        __syncthreads();

        // ---- compute 8 k-steps of 16
#pragma unroll
        for (int ks = 0; ks < 8; ++ks) {
            uint32_t ah[2][4], al[2][4];
#pragma unroll
            for (int im = 0; im < 2; ++im) {
                const int row = wm * 32 + im * 16 + a_row;
                const int g   = ks * 2 + a_gh;
                const uint32_t off = row * 256 + ((g ^ (row & 7)) << 4);
                ldmatrix_x4(ah[im], sAhi + off);
                ldmatrix_x4(al[im], sAlo + off);
            }
            uint32_t bh[4][4], bl[4][4];
#pragma unroll
            for (int bp = 0; bp < 4; ++bp) {
                const int row = wn * 64 + bp * 16 + b_nof;
                const int g   = ks * 2 + b_gh;
                const uint32_t off = row * 256 + ((g ^ (row & 7)) << 4);
                ldmatrix_x4(bh[bp], sBhi + off);
                ldmatrix_x4(bl[bp], sBlo + off);
            }
#pragma unroll
            for (int im = 0; im < 2; ++im)
#pragma unroll
                for (int in = 0; in < 8; ++in) {
                    const uint32_t* Bh = &bh[in >> 1][(in & 1) * 2];
                    const uint32_t* Bl = &bl[in >> 1][(in & 1) * 2];
                    mma_bf16(acc[im][in], ah[im], Bh);
                    mma_bf16(acc[im][in], ah[im], Bl);
                    mma_bf16(acc[im][in], al[im], Bh);
                }
        }
    }

    // ---- epilogue: D(16x8) lanes: c0/c1 at (r, c..c+1), c2/c3 at (r+8, c..c+1)
    const int r  = lane >> 2;
    const int cc = (lane & 3) * 2;
#pragma unroll
    for (int im = 0; im < 2; ++im) {
        const int mrow = m0 + wm * 32 + im * 16 + r;
#pragma unroll
        for (int in = 0; in < 8; ++in) {
            const int ncol = wn * 64 + in * 8 + cc;           // 0..127 in slab
            const float2 bv = __ldg((const float2*)(bia + nloc0 + ncol));
            float* p0 = &g_S[(size_t)mrow * 1024 + bx * 128 + ncol];
            float* p1 = p0 + 8 * 1024;
            *(float2*)p0 = make_float2(acc[im][in][0] + bv.x, acc[im][in][1] + bv.y);
            *(float2*)p1 = make_float2(acc[im][in][2] + bv.x, acc[im][in][3] + bv.y);
        }
    }
}

// ---------------------------------------------------------------------------
// Kernel B: per (batch, segment) attention (unchanged, passing at R3)
// ---------------------------------------------------------------------------
#define ATTN_SMEM_FLOATS (256 * 128 + 128 * 128 + 256 * 32)   // 57344
#define ATTN_SMEM_BYTES  (ATTN_SMEM_FLOATS * 4)               // 229376

__global__ void __launch_bounds__(256, 1) attn_kernel(float* __restrict__ out)
{
    extern __shared__ float sm[];
    float* sKT   = sm;
    float* probs = sm + 256 * 128;
    float* s1T   = sm + 256 * 128 + 128 * 128;

    const int seg = blockIdx.x;
    const int b   = blockIdx.y;
    const int n   = (seg == 0) ? 103 : (seg == 1) ? 119 : 11;
    const int off = (seg == 0) ? 0   : (seg == 1) ? 103 : 222;

    const size_t rowbase = ((size_t)b * SEQ + off) * 1024;
    const int tid = threadIdx.x;

    for (int slot = tid; slot < 128 * 64; slot += 256) {
        const int j  = slot >> 6;
        const int kv = slot & 63;
        float4 v = make_float4(0.f, 0.f, 0.f, 0.f);
        if (j < n) v = *(const float4*)&g_S[rowbase + (size_t)j * 1024 + 512 + kv * 4];
        const int col = (((j >> 2) ^ (kv & 7)) << 2) + (j & 3);
        const int k0  = kv * 4;
        sKT[(k0 + 0) * 128 + col] = v.x;
        sKT[(k0 + 1) * 128 + col] = v.y;
        sKT[(k0 + 2) * 128 + col] = v.z;
        sKT[(k0 + 3) * 128 + col] = v.w;
    }
    __syncthreads();

    const int jx  = tid & 31;
    const int iy  = tid >> 5;
    const int nch = (n + 31) >> 5;

    for (int ch = 0; ch < nch; ++ch) {
        const int i0 = ch << 5;

        for (int slot = tid; slot < 32 * 64; slot += 256) {
            const int il = slot >> 6;
            const int kv = slot & 63;
            const int gi = i0 + il;
            float4 v = make_float4(0.f, 0.f, 0.f, 0.f);
            if (gi < n) v = *(const float4*)&g_S[rowbase + (size_t)gi * 1024 + 256 + kv * 4];
            const int col = (((il >> 2) ^ (kv & 7)) << 2) + (il & 3);
            const int k0  = kv * 4;
            s1T[(k0 + 0) * 32 + col] = v.x;
            s1T[(k0 + 1) * 32 + col] = v.y;
            s1T[(k0 + 2) * 32 + col] = v.z;
            s1T[(k0 + 3) * 32 + col] = v.w;
        }
        __syncthreads();

        float accS[4][4];
#pragma unroll
        for (int i = 0; i < 4; ++i)
#pragma unroll
            for (int j = 0; j < 4; ++j) accS[i][j] = 0.0f;

#pragma unroll 8
        for (int k = 0; k < 256; ++k) {
            const int f = (k >> 2) & 7;
            const float4 a = *(const float4*)(s1T + k * 32  + (((iy ^ f)) << 2));
            const float4 q = *(const float4*)(sKT + k * 128 + (((jx ^ f)) << 2));
            const float a4[4] = {a.x, a.y, a.z, a.w};
            const float q4[4] = {q.x, q.y, q.z, q.w};
#pragma unroll
            for (int i = 0; i < 4; ++i)
#pragma unroll
                for (int j = 0; j < 4; ++j)
                    accS[i][j] = fmaf(a4[i], q4[j], accS[i][j]);
        }

#pragma unroll
        for (int ii = 0; ii < 4; ++ii) {
            const int gi = i0 + iy * 4 + ii;
            float4 p;
            p.x = accS[ii][0] * SCALE + ((gi == jx * 4 + 0) ? NEG : 0.f);
            p.y = accS[ii][1] * SCALE + ((gi == jx * 4 + 1) ? NEG : 0.f);
            p.z = accS[ii][2] * SCALE + ((gi == jx * 4 + 2) ? NEG : 0.f);
            p.w = accS[ii][3] * SCALE + ((gi == jx * 4 + 3) ? NEG : 0.f);
            *(float4*)&probs[gi * 128 + jx * 4] = p;
        }
        __syncthreads();

        {
            const int lane = tid & 31;
            const int w    = tid >> 5;
#pragma unroll
            for (int r = 0; r < 4; ++r) {
                const int gi = i0 + w * 4 + r;
                if (gi >= n) break;
                float mx = -1e30f;
                for (int j = lane; j < n; j += 32)
                    mx = fmaxf(mx, probs[gi * 128 + j]);
#pragma unroll
                for (int o = 16; o; o >>= 1)
                    mx = fmaxf(mx, __shfl_xor_sync(0xffffffffu, mx, o));
                float ssum = 0.f;
                for (int j = lane; j < n; j += 32) {
                    const float e = __expf(probs[gi * 128 + j] - mx);
                    probs[gi * 128 + j] = e;
                    ssum += e;
                }
#pragma unroll
                for (int o = 16; o; o >>= 1)
                    ssum += __shfl_xor_sync(0xffffffffu, ssum, o);
                const float inv = 1.0f / ssum;
                for (int j = lane; j < n; j += 32)
                    probs[gi * 128 + j] *= inv;
            }
        }
        __syncthreads();
    }

    for (int slot = tid; slot < n * 64; slot += 256) {
        const int j  = slot >> 6;
        const int kv = slot & 63;
        *(float4*)&sm[j * 256 + kv * 4] =
            *(const float4*)&g_S[rowbase + (size_t)j * 1024 + 768 + kv * 4];
    }
    __syncthreads();

    const int tx = tid & 31;
    const int ty = tid >> 5;

    for (int ch = 0; ch < nch; ++ch) {
        const int i0 = ch << 5;
        const int ib = i0 + ty * 4;

        float acc[4][8];
#pragma unroll
        for (int i = 0; i < 4; ++i)
#pragma unroll
            for (int h = 0; h < 8; ++h) acc[i][h] = 0.0f;

        for (int j = 0; j < n; ++j) {
            const float4 v0 = *(const float4*)&sm[j * 256 + tx * 4];
            const float4 v1 = *(const float4*)&sm[j * 256 + 128 + tx * 4];
            const float p[4] = {probs[(ib + 0) * 128 + j],
                                probs[(ib + 1) * 128 + j],
                                probs[(ib + 2) * 128 + j],
                                probs[(ib + 3) * 128 + j]};
            const float v[8] = {v0.x, v0.y, v0.z, v0.w, v1.x, v1.y, v1.z, v1.w};
#pragma unroll
            for (int i = 0; i < 4; ++i)
#pragma unroll
                for (int h = 0; h < 8; ++h)
                    acc[i][h] = fmaf(p[i], v[h], acc[i][h]);
        }

#pragma unroll
        for (int ii = 0; ii < 4; ++ii) {
            const int gi = ib + ii;
            if (gi < n) {
                const float4 a0 = *(const float4*)&g_S[rowbase + (size_t)gi * 1024 + tx * 4];
                const float4 a1 = *(const float4*)&g_S[rowbase + (size_t)gi * 1024 + 128 + tx * 4];
                float4 o0, o1;
                o0.x = a0.x - acc[ii][0]; o0.y = a0.y - acc[ii][1];
                o0.z = a0.z - acc[ii][2]; o0.w = a0.w - acc[ii][3];
                o1.x = a1.x - acc[ii][4]; o1.y = a1.y - acc[ii][5];
                o1.z = a1.z - acc[ii][6]; o1.w = a1.w - acc[ii][7];
                const size_t ob = ((size_t)b * SEQ + off + gi) * 256;
                *(float4*)&out[ob + tx * 4]       = o0;
                *(float4*)&out[ob + 128 + tx * 4] = o1;
            }
        }
    }
}

// ---------------------------------------------------------------------------
extern "C" void kernel_launch(void* const* d_in, const int* in_sizes, int n_in,
                              void* d_out, int out_size)
{
    const float* toks = (const float*)d_in[0];
    const float* W0   = (const float*)d_in[1];
    const float* b0   = (const float*)d_in[2];
    const float* W1   = (const float*)d_in[3];
    const float* b1   = (const float*)d_in[4];
    const float* W2   = (const float*)d_in[5];
    const float* b2   = (const float*)d_in[6];
    const float* W3   = (const float*)d_in[7];
    const float* b3   = (const float*)d_in[8];
    float* out = (float*)d_out;

    cudaFuncSetAttribute(proj_mma_kernel,
                         cudaFuncAttributeMaxDynamicSharedMemorySize, PJ_SMEM);
    dim3 gA(8, MROWS / 128);
    proj_mma_kernel<<<gA, 256, PJ_SMEM>>>(toks, W0, b0, W1, b1, W2, b2, W3, b3);

    cudaFuncSetAttribute(attn_kernel,
                         cudaFuncAttributeMaxDynamicSharedMemorySize, ATTN_SMEM_BYTES);
    dim3 gB(3, BATCH);
    attn_kernel<<<gB, 256, ATTN_SMEM_BYTES>>>(out);
}

// round 6
// speedup vs baseline: 1.9633x; 1.3109x over previous
#include <cuda_runtime.h>
#include <cuda_bf16.h>
#include <cstdint>
#include <math.h>

#define HIDDEN 256
#define SEQ    233
#define BATCH  1024
#define MROWS  (BATCH * SEQ)          // 238592 = 128 * 1864
#define SCALE  0.0625f                // 1/sqrt(256)
#define NEG    (-10000.0f)

// Scratch: s0 fp32, s1/s2/s3 as bf16 hi/lo (cols: s1 0..255, s2 256..511, s3 512..767)
static __device__ float          g_S0 [(size_t)MROWS * 256];
static __device__ __nv_bfloat16  g_Shi[(size_t)MROWS * 768];
static __device__ __nv_bfloat16  g_Slo[(size_t)MROWS * 768];

__device__ __forceinline__ uint32_t smem_u32(const void* p) {
    uint32_t a;
    asm("{ .reg .u64 t; cvta.to.shared.u64 t, %1; cvt.u32.u64 %0, t; }" : "=r"(a) : "l"(p));
    return a;
}
__device__ __forceinline__ uint32_t b2u(__nv_bfloat162 h) {
    return *reinterpret_cast<uint32_t*>(&h);
}
__device__ __forceinline__ void ldmatrix_x4(uint32_t* r, uint32_t addr) {
    asm volatile("ldmatrix.sync.aligned.m8n8.x4.shared.b16 {%0,%1,%2,%3}, [%4];"
                 : "=r"(r[0]), "=r"(r[1]), "=r"(r[2]), "=r"(r[3]) : "r"(addr));
}
__device__ __forceinline__ void ldmatrix_x4_t(uint32_t* r, uint32_t addr) {
    asm volatile("ldmatrix.sync.aligned.m8n8.x4.trans.shared.b16 {%0,%1,%2,%3}, [%4];"
                 : "=r"(r[0]), "=r"(r[1]), "=r"(r[2]), "=r"(r[3]) : "r"(addr));
}
__device__ __forceinline__ void mma_bf16(float* c, const uint32_t* a, const uint32_t* b) {
    asm volatile(
        "mma.sync.aligned.m16n8k16.row.col.f32.bf16.bf16.f32 "
        "{%0,%1,%2,%3}, {%4,%5,%6,%7}, {%8,%9}, {%0,%1,%2,%3};"
        : "+f"(c[0]), "+f"(c[1]), "+f"(c[2]), "+f"(c[3])
        : "r"(a[0]), "r"(a[1]), "r"(a[2]), "r"(a[3]), "r"(b[0]), "r"(b[1]));
}
__device__ __forceinline__ void split8(const float4 v0, const float4 v1,
                                       uint4& hi, uint4& lo) {
    __nv_bfloat162 h0 = __floats2bfloat162_rn(v0.x, v0.y);
    __nv_bfloat162 h1 = __floats2bfloat162_rn(v0.z, v0.w);
    __nv_bfloat162 h2 = __floats2bfloat162_rn(v1.x, v1.y);
    __nv_bfloat162 h3 = __floats2bfloat162_rn(v1.z, v1.w);
    float2 f0 = __bfloat1622float2(h0), f1 = __bfloat1622float2(h1);
    float2 f2 = __bfloat1622float2(h2), f3 = __bfloat1622float2(h3);
    __nv_bfloat162 l0 = __floats2bfloat162_rn(v0.x - f0.x, v0.y - f0.y);
    __nv_bfloat162 l1 = __floats2bfloat162_rn(v0.z - f1.x, v0.w - f1.y);
    __nv_bfloat162 l2 = __floats2bfloat162_rn(v1.x - f2.x, v1.y - f2.y);
    __nv_bfloat162 l3 = __floats2bfloat162_rn(v1.z - f3.x, v1.w - f3.y);
    hi = make_uint4(b2u(h0), b2u(h1), b2u(h2), b2u(h3));
    lo = make_uint4(b2u(l0), b2u(l1), b2u(l2), b2u(l3));
}

// ===========================================================================
// Kernel A (mma.sync bf16 hi/lo), unchanged compute, new epilogue targets.
// ===========================================================================
#define PJ_SMEM 131072

__global__ void __launch_bounds__(256, 1) proj_mma_kernel(
    const float* __restrict__ X,
    const float* __restrict__ W0, const float* __restrict__ B0,
    const float* __restrict__ W1, const float* __restrict__ B1,
    const float* __restrict__ W2, const float* __restrict__ B2,
    const float* __restrict__ W3, const float* __restrict__ B3)
{
    extern __shared__ __align__(16) char smp[];
    const uint32_t sAhi = smem_u32(smp);
    const uint32_t sAlo = sAhi + 32768;
    const uint32_t sBhi = sAhi + 65536;
    const uint32_t sBlo = sAhi + 98304;

    const int tid  = threadIdx.x;
    const int wid  = tid >> 5;
    const int lane = tid & 31;
    const int wm   = wid & 3;
    const int wn   = wid >> 2;

    const int bx = blockIdx.x;         // 0..7 : 128-col slab of the 1024 cols
    const int m0 = blockIdx.y * 128;
    const int wsel = bx >> 1;
    const float* W   = (wsel == 0) ? W0 : (wsel == 1) ? W1 : (wsel == 2) ? W2 : W3;
    const float* bia = (wsel == 0) ? B0 : (wsel == 1) ? B1 : (wsel == 2) ? B2 : B3;
    const int nloc0 = (bx & 1) * 128;

    float acc[2][8][4];
#pragma unroll
    for (int i = 0; i < 2; ++i)
#pragma unroll
        for (int j = 0; j < 8; ++j)
#pragma unroll
            for (int q = 0; q < 4; ++q) acc[i][j][q] = 0.0f;

    const int a_row = lane & 15;
    const int a_gh  = lane >> 4;
    const int b_nof = (lane & 7) + ((lane & 16) ? 8 : 0);
    const int b_gh  = (lane >> 3) & 1;

#pragma unroll 1
    for (int c = 0; c < 2; ++c) {
        if (c) __syncthreads();

#pragma unroll
        for (int it = 0; it < 8; ++it) {
            const int gi  = tid + it * 256;
            const int row = gi >> 4;
            const int g   = gi & 15;
            const float* src = X + (size_t)(m0 + row) * HIDDEN + c * 128 + g * 8;
            uint4 hi, lo;
            split8(__ldg((const float4*)src), __ldg((const float4*)(src + 4)), hi, lo);
            const uint32_t off = row * 256 + ((g ^ (row & 7)) << 4);
            *(uint4*)(smp + off)         = hi;
            *(uint4*)(smp + 32768 + off) = lo;
        }
#pragma unroll
        for (int it = 0; it < 8; ++it) {
            const int gi  = tid + it * 256;
            const int row = gi >> 4;
            const int g   = gi & 15;
            const float* src = W + (size_t)(nloc0 + row) * HIDDEN + c * 128 + g * 8;
            uint4 hi, lo;
            split8(__ldg((const float4*)src), __ldg((const float4*)(src + 4)), hi, lo);
            const uint32_t off = row * 256 + ((g ^ (row & 7)) << 4);
            *(uint4*)(smp + 65536 + off) = hi;
            *(uint4*)(smp + 98304 + off) = lo;
        }
        __syncthreads();

#pragma unroll
        for (int ks = 0; ks < 8; ++ks) {
            uint32_t ah[2][4], al[2][4];
#pragma unroll
            for (int im = 0; im < 2; ++im) {
                const int row = wm * 32 + im * 16 + a_row;
                const int g   = ks * 2 + a_gh;
                const uint32_t off = row * 256 + ((g ^ (row & 7)) << 4);
                ldmatrix_x4(ah[im], sAhi + off);
                ldmatrix_x4(al[im], sAlo + off);
            }
            uint32_t bh[4][4], bl[4][4];
#pragma unroll
            for (int bp = 0; bp < 4; ++bp) {
                const int row = wn * 64 + bp * 16 + b_nof;
                const int g   = ks * 2 + b_gh;
                const uint32_t off = row * 256 + ((g ^ (row & 7)) << 4);
                ldmatrix_x4(bh[bp], sBhi + off);
                ldmatrix_x4(bl[bp], sBlo + off);
            }
#pragma unroll
            for (int im = 0; im < 2; ++im)
#pragma unroll
                for (int in = 0; in < 8; ++in) {
                    const uint32_t* Bh = &bh[in >> 1][(in & 1) * 2];
                    const uint32_t* Bl = &bl[in >> 1][(in & 1) * 2];
                    mma_bf16(acc[im][in], ah[im], Bh);
                    mma_bf16(acc[im][in], ah[im], Bl);
                    mma_bf16(acc[im][in], al[im], Bh);
                }
        }
    }

    // ---- epilogue: bx 0,1 -> g_S0 fp32; bx>=2 -> g_Shi/g_Slo bf16 hi/lo
    const int r  = lane >> 2;
    const int cc = (lane & 3) * 2;
#pragma unroll
    for (int im = 0; im < 2; ++im) {
        const int mr = m0 + wm * 32 + im * 16 + r;
#pragma unroll
        for (int in = 0; in < 8; ++in) {
            const int ncol = wn * 64 + in * 8 + cc;
            const float2 bv = __ldg((const float2*)(bia + nloc0 + ncol));
            const float v00 = acc[im][in][0] + bv.x, v01 = acc[im][in][1] + bv.y;
            const float v10 = acc[im][in][2] + bv.x, v11 = acc[im][in][3] + bv.y;
            if (bx < 2) {
                *(float2*)&g_S0[(size_t)mr * 256 + bx * 128 + ncol]       = make_float2(v00, v01);
                *(float2*)&g_S0[(size_t)(mr + 8) * 256 + bx * 128 + ncol] = make_float2(v10, v11);
            } else {
                const int c3 = (bx - 2) * 128 + ncol;
                __nv_bfloat162 h0 = __floats2bfloat162_rn(v00, v01);
                float2 f0 = __bfloat1622float2(h0);
                __nv_bfloat162 l0 = __floats2bfloat162_rn(v00 - f0.x, v01 - f0.y);
                __nv_bfloat162 h1 = __floats2bfloat162_rn(v10, v11);
                float2 f1 = __bfloat1622float2(h1);
                __nv_bfloat162 l1 = __floats2bfloat162_rn(v10 - f1.x, v11 - f1.y);
                *(uint32_t*)&g_Shi[(size_t)mr * 768 + c3]       = b2u(h0);
                *(uint32_t*)&g_Slo[(size_t)mr * 768 + c3]       = b2u(l0);
                *(uint32_t*)&g_Shi[(size_t)(mr + 8) * 768 + c3] = b2u(h1);
                *(uint32_t*)&g_Slo[(size_t)(mr + 8) * 768 + c3] = b2u(l1);
            }
        }
    }
}

// ===========================================================================
// Kernel B (mma.sync attention): per (batch, segment), n padded to 128.
// SMEM map:
//   [0,128K):    phase1 Qhi/Qlo/Khi/Klo [128][128]bf16 (32KB each)
//                phase3 sVhi/sVlo [128 j][256 h]bf16 (64KB each)
//   [128K, +61952): scores fp32 [120][129]
//   [193024, +32768): sP bf16 [128][128] (swizzled like A tiles)
// ===========================================================================
#define AT_SCORES 131072
#define AT_SP     193024
#define AT_SMEM   225792

__global__ void __launch_bounds__(256, 1) attn_mma_kernel(float* __restrict__ out)
{
    extern __shared__ __align__(16) char smp[];
    const uint32_t sQhi = smem_u32(smp);
    const uint32_t sQlo = sQhi + 32768;
    const uint32_t sKhi = sQhi + 65536;
    const uint32_t sKlo = sQhi + 98304;
    const uint32_t sVhi = sQhi;            // phase3 alias
    const uint32_t sVlo = sQhi + 65536;
    float* sscore = (float*)(smp + AT_SCORES);
    const uint32_t sP = sQhi + AT_SP;

    const int seg = blockIdx.x;
    const int b   = blockIdx.y;
    const int n   = (seg == 0) ? 103 : (seg == 1) ? 119 : 11;
    const int off = (seg == 0) ? 0   : (seg == 1) ? 103 : 222;
    const size_t grow0 = (size_t)b * SEQ + off;

    const int tid  = threadIdx.x;
    const int wid  = tid >> 5;
    const int lane = tid & 31;
    const int wm   = wid & 3;
    const int wn   = wid >> 2;

    const int a_row = lane & 15;
    const int a_gh  = lane >> 4;
    const int b_nof = (lane & 7) + ((lane & 16) ? 8 : 0);
    const int b_gh  = (lane >> 3) & 1;

    float acc[2][8][4];
#pragma unroll
    for (int i = 0; i < 2; ++i)
#pragma unroll
        for (int j = 0; j < 8; ++j)
#pragma unroll
            for (int q = 0; q < 4; ++q) acc[i][j][q] = 0.0f;

    // ============ phase 1: scores = s1 . s2^T (3-pass hi/lo), 2 K-chunks
#pragma unroll 1
    for (int kc = 0; kc < 2; ++kc) {
        if (kc) __syncthreads();
        // Q tiles (s1: cols 0..255 of g_Shi/lo)
#pragma unroll
        for (int it = 0; it < 8; ++it) {
            const int gi = tid + it * 256;
            const int row = gi >> 4, g = gi & 15;
            const size_t src = (grow0 + row) * 768 + kc * 128 + g * 8;
            uint4 vh = make_uint4(0,0,0,0), vl = make_uint4(0,0,0,0);
            if (row < n) { vh = *(const uint4*)&g_Shi[src]; vl = *(const uint4*)&g_Slo[src]; }
            const uint32_t o = row * 256 + ((g ^ (row & 7)) << 4);
            *(uint4*)(smp + o)         = vh;
            *(uint4*)(smp + 32768 + o) = vl;
        }
        // K tiles (s2: cols 256..511)
#pragma unroll
        for (int it = 0; it < 8; ++it) {
            const int gi = tid + it * 256;
            const int row = gi >> 4, g = gi & 15;
            const size_t src = (grow0 + row) * 768 + 256 + kc * 128 + g * 8;
            uint4 vh = make_uint4(0,0,0,0), vl = make_uint4(0,0,0,0);
            if (row < n) { vh = *(const uint4*)&g_Shi[src]; vl = *(const uint4*)&g_Slo[src]; }
            const uint32_t o = row * 256 + ((g ^ (row & 7)) << 4);
            *(uint4*)(smp + 65536 + o) = vh;
            *(uint4*)(smp + 98304 + o) = vl;
        }
        __syncthreads();

#pragma unroll
        for (int ks = 0; ks < 8; ++ks) {
            uint32_t ah[2][4], al[2][4];
#pragma unroll
            for (int im = 0; im < 2; ++im) {
                const int row = wm * 32 + im * 16 + a_row;
                const int g   = ks * 2 + a_gh;
                const uint32_t o = row * 256 + ((g ^ (row & 7)) << 4);
                ldmatrix_x4(ah[im], sQhi + o);
                ldmatrix_x4(al[im], sQlo + o);
            }
            uint32_t bh[4][4], bl[4][4];
#pragma unroll
            for (int bp = 0; bp < 4; ++bp) {
                const int row = wn * 64 + bp * 16 + b_nof;
                const int g   = ks * 2 + b_gh;
                const uint32_t o = row * 256 + ((g ^ (row & 7)) << 4);
                ldmatrix_x4(bh[bp], sKhi + o);
                ldmatrix_x4(bl[bp], sKlo + o);
            }
#pragma unroll
            for (int im = 0; im < 2; ++im)
#pragma unroll
                for (int in = 0; in < 8; ++in) {
                    const uint32_t* Bh = &bh[in >> 1][(in & 1) * 2];
                    const uint32_t* Bl = &bl[in >> 1][(in & 1) * 2];
                    mma_bf16(acc[im][in], ah[im], Bh);
                    mma_bf16(acc[im][in], ah[im], Bl);
                    mma_bf16(acc[im][in], al[im], Bh);
                }
        }
        __syncthreads();
    }

    // ============ phase 2: scale + mask -> scores SMEM -> softmax -> sP bf16
    {
        const int r  = lane >> 2;
        const int cc = (lane & 3) * 2;
#pragma unroll
        for (int im = 0; im < 2; ++im) {
            const int g1 = wm * 32 + im * 16 + r;
            const int g2 = g1 + 8;
#pragma unroll
            for (int in = 0; in < 8; ++in) {
                const int col = wn * 64 + in * 8 + cc;
                if (g1 < n) {
                    float vx = (col     >= n) ? NEG : acc[im][in][0] * SCALE + ((col     == g1) ? NEG : 0.f);
                    float vy = (col + 1 >= n) ? NEG : acc[im][in][1] * SCALE + ((col + 1 == g1) ? NEG : 0.f);
                    sscore[g1 * 129 + col]     = vx;
                    sscore[g1 * 129 + col + 1] = vy;
                }
                if (g2 < n) {
                    float vx = (col     >= n) ? NEG : acc[im][in][2] * SCALE + ((col     == g2) ? NEG : 0.f);
                    float vy = (col + 1 >= n) ? NEG : acc[im][in][3] * SCALE + ((col + 1 == g2) ? NEG : 0.f);
                    sscore[g2 * 129 + col]     = vx;
                    sscore[g2 * 129 + col + 1] = vy;
                }
            }
        }
    }
    __syncthreads();

    // softmax: 8 warps x 16 rows
#pragma unroll 1
    for (int rr = 0; rr < 16; ++rr) {
        const int gi = rr * 8 + wid;
        if (gi < n) {
            float* rowp = &sscore[gi * 129];
            float mx = -1e30f;
#pragma unroll
            for (int j = lane; j < 128; j += 32) mx = fmaxf(mx, rowp[j]);
#pragma unroll
            for (int o = 16; o; o >>= 1) mx = fmaxf(mx, __shfl_xor_sync(0xffffffffu, mx, o));
            float ssum = 0.f;
#pragma unroll
            for (int j = lane; j < 128; j += 32) {
                const float e = __expf(rowp[j] - mx);
                rowp[j] = e;
                ssum += e;
            }
#pragma unroll
            for (int o = 16; o; o >>= 1) ssum += __shfl_xor_sync(0xffffffffu, ssum, o);
            const float inv = 1.0f / ssum;
#pragma unroll
            for (int j = lane; j < 32*4; j += 32) rowp[j] *= inv;
        }
    }
    __syncthreads();

    // ============ load V (s3: cols 512..767) + convert probs -> sP
#pragma unroll
    for (int it = 0; it < 16; ++it) {
        const int gi = tid + it * 256;            // 0..4095
        const int j = gi >> 5, gg = gi & 31;
        const size_t src = (grow0 + j) * 768 + 512 + gg * 8;
        uint4 vh = make_uint4(0,0,0,0), vl = make_uint4(0,0,0,0);
        if (j < n) { vh = *(const uint4*)&g_Shi[src]; vl = *(const uint4*)&g_Slo[src]; }
        const uint32_t o = j * 512 + ((gg ^ (j & 7)) << 4);
        *(uint4*)(smp + o)         = vh;
        *(uint4*)(smp + 65536 + o) = vl;
    }
#pragma unroll
    for (int it = 0; it < 8; ++it) {
        const int gi = tid + it * 256;            // 0..2047
        const int row = gi >> 4, g = gi & 15;
        uint4 v = make_uint4(0, 0, 0, 0);
        if (row < n) {
            const float* rp = &sscore[row * 129 + g * 8];
            v.x = b2u(__floats2bfloat162_rn(rp[0], rp[1]));
            v.y = b2u(__floats2bfloat162_rn(rp[2], rp[3]));
            v.z = b2u(__floats2bfloat162_rn(rp[4], rp[5]));
            v.w = b2u(__floats2bfloat162_rn(rp[6], rp[7]));
        }
        *(uint4*)(smp + AT_SP + row * 256 + ((g ^ (row & 7)) << 4)) = v;
    }
    __syncthreads();

    // ============ phase 3: out = s0 - probs @ s3, two 128-col halves
#pragma unroll 1
    for (int hb = 0; hb < 2; ++hb) {
        float acc2[2][8][4];
#pragma unroll
        for (int i = 0; i < 2; ++i)
#pragma unroll
            for (int j = 0; j < 8; ++j)
#pragma unroll
                for (int q = 0; q < 4; ++q) acc2[i][j][q] = 0.0f;

#pragma unroll
        for (int ks = 0; ks < 8; ++ks) {
            uint32_t ap[2][4];
#pragma unroll
            for (int im = 0; im < 2; ++im) {
                const int row = wm * 32 + im * 16 + a_row;
                const int g   = ks * 2 + a_gh;
                ldmatrix_x4(ap[im], sP + row * 256 + ((g ^ (row & 7)) << 4));
            }
            uint32_t bvh[4][4], bvl[4][4];
#pragma unroll
            for (int bp = 0; bp < 4; ++bp) {
                const int jrow = ks * 16 + (lane & 15);
                const int gg   = hb * 16 + wn * 8 + bp * 2 + (lane >> 4);
                const uint32_t o = jrow * 512 + ((gg ^ (jrow & 7)) << 4);
                ldmatrix_x4_t(bvh[bp], sVhi + o);
                ldmatrix_x4_t(bvl[bp], sVlo + o);
            }
#pragma unroll
            for (int im = 0; im < 2; ++im)
#pragma unroll
                for (int in = 0; in < 8; ++in) {
                    const uint32_t* Bh = &bvh[in >> 1][(in & 1) * 2];
                    const uint32_t* Bl = &bvl[in >> 1][(in & 1) * 2];
                    mma_bf16(acc2[im][in], ap[im], Bh);
                    mma_bf16(acc2[im][in], ap[im], Bl);
                }
        }

        // epilogue: out = s0 - acc2
        const int r  = lane >> 2;
        const int cc = (lane & 3) * 2;
#pragma unroll
        for (int im = 0; im < 2; ++im) {
            const int g1 = wm * 32 + im * 16 + r;
#pragma unroll
            for (int in = 0; in < 8; ++in) {
                const int h = hb * 128 + wn * 64 + in * 8 + cc;
                if (g1 < n) {
                    const float2 s0 = __ldg((const float2*)&g_S0[(grow0 + g1) * 256 + h]);
                    *(float2*)&out[(grow0 + g1) * 256 + h] =
                        make_float2(s0.x - acc2[im][in][0], s0.y - acc2[im][in][1]);
                }
                const int g2 = g1 + 8;
                if (g2 < n) {
                    const float2 s0 = __ldg((const float2*)&g_S0[(grow0 + g2) * 256 + h]);
                    *(float2*)&out[(grow0 + g2) * 256 + h] =
                        make_float2(s0.x - acc2[im][in][2], s0.y - acc2[im][in][3]);
                }
            }
        }
    }
}

// ---------------------------------------------------------------------------
extern "C" void kernel_launch(void* const* d_in, const int* in_sizes, int n_in,
                              void* d_out, int out_size)
{
    const float* toks = (const float*)d_in[0];
    const float* W0   = (const float*)d_in[1];
    const float* b0   = (const float*)d_in[2];
    const float* W1   = (const float*)d_in[3];
    const float* b1   = (const float*)d_in[4];
    const float* W2   = (const float*)d_in[5];
    const float* b2   = (const float*)d_in[6];
    const float* W3   = (const float*)d_in[7];
    const float* b3   = (const float*)d_in[8];
    float* out = (float*)d_out;

    cudaFuncSetAttribute(proj_mma_kernel,
                         cudaFuncAttributeMaxDynamicSharedMemorySize, PJ_SMEM);
    dim3 gA(8, MROWS / 128);
    proj_mma_kernel<<<gA, 256, PJ_SMEM>>>(toks, W0, b0, W1, b1, W2, b2, W3, b3);

    cudaFuncSetAttribute(attn_mma_kernel,
                         cudaFuncAttributeMaxDynamicSharedMemorySize, AT_SMEM);
    dim3 gB(3, BATCH);
    attn_mma_kernel<<<gB, 256, AT_SMEM>>>(out);
}

// round 7
// speedup vs baseline: 2.0854x; 1.0622x over previous
#include <cuda_runtime.h>
#include <cuda_bf16.h>
#include <cstdint>
#include <math.h>

#define HIDDEN 256
#define SEQ    233
#define BATCH  1024
#define MROWS  (BATCH * SEQ)          // 238592 = 128 * 1864
#define SCALE  0.0625f                // 1/sqrt(256)
#define NEG    (-10000.0f)

// Scratch buffers
static __device__ float          g_S0 [(size_t)MROWS * 256];
static __device__ __nv_bfloat16  g_Shi[(size_t)MROWS * 768];
static __device__ __nv_bfloat16  g_Slo[(size_t)MROWS * 768];
static __device__ __nv_bfloat16  g_Xhi[(size_t)MROWS * 256];
static __device__ __nv_bfloat16  g_Xlo[(size_t)MROWS * 256];
static __device__ __nv_bfloat16  g_Whi[1024 * 256];
static __device__ __nv_bfloat16  g_Wlo[1024 * 256];

__device__ __forceinline__ uint32_t smem_u32(const void* p) {
    uint32_t a;
    asm("{ .reg .u64 t; cvta.to.shared.u64 t, %1; cvt.u32.u64 %0, t; }" : "=r"(a) : "l"(p));
    return a;
}
__device__ __forceinline__ uint32_t b2u(__nv_bfloat162 h) {
    return *reinterpret_cast<uint32_t*>(&h);
}
__device__ __forceinline__ void ldmatrix_x4(uint32_t* r, uint32_t addr) {
    asm volatile("ldmatrix.sync.aligned.m8n8.x4.shared.b16 {%0,%1,%2,%3}, [%4];"
                 : "=r"(r[0]), "=r"(r[1]), "=r"(r[2]), "=r"(r[3]) : "r"(addr));
}
__device__ __forceinline__ void ldmatrix_x4_t(uint32_t* r, uint32_t addr) {
    asm volatile("ldmatrix.sync.aligned.m8n8.x4.trans.shared.b16 {%0,%1,%2,%3}, [%4];"
                 : "=r"(r[0]), "=r"(r[1]), "=r"(r[2]), "=r"(r[3]) : "r"(addr));
}
__device__ __forceinline__ void mma_bf16(float* c, const uint32_t* a, const uint32_t* b) {
    asm volatile(
        "mma.sync.aligned.m16n8k16.row.col.f32.bf16.bf16.f32 "
        "{%0,%1,%2,%3}, {%4,%5,%6,%7}, {%8,%9}, {%0,%1,%2,%3};"
        : "+f"(c[0]), "+f"(c[1]), "+f"(c[2]), "+f"(c[3])
        : "r"(a[0]), "r"(a[1]), "r"(a[2]), "r"(a[3]), "r"(b[0]), "r"(b[1]));
}
__device__ __forceinline__ void split8(const float4 v0, const float4 v1,
                                       uint4& hi, uint4& lo) {
    __nv_bfloat162 h0 = __floats2bfloat162_rn(v0.x, v0.y);
    __nv_bfloat162 h1 = __floats2bfloat162_rn(v0.z, v0.w);
    __nv_bfloat162 h2 = __floats2bfloat162_rn(v1.x, v1.y);
    __nv_bfloat162 h3 = __floats2bfloat162_rn(v1.z, v1.w);
    float2 f0 = __bfloat1622float2(h0), f1 = __bfloat1622float2(h1);
    float2 f2 = __bfloat1622float2(h2), f3 = __bfloat1622float2(h3);
    __nv_bfloat162 l0 = __floats2bfloat162_rn(v0.x - f0.x, v0.y - f0.y);
    __nv_bfloat162 l1 = __floats2bfloat162_rn(v0.z - f1.x, v0.w - f1.y);
    __nv_bfloat162 l2 = __floats2bfloat162_rn(v1.x - f2.x, v1.y - f2.y);
    __nv_bfloat162 l3 = __floats2bfloat162_rn(v1.z - f3.x, v1.w - f3.y);
    hi = make_uint4(b2u(h0), b2u(h1), b2u(h2), b2u(h3));
    lo = make_uint4(b2u(l0), b2u(l1), b2u(l2), b2u(l3));
}

#define CP_A16(dst, src) asm volatile("cp.async.cg.shared.global [%0], [%1], 16;" :: "r"(dst), "l"(src))
#define CP_COMMIT()      asm volatile("cp.async.commit_group;")
#define CP_WAIT(n)       asm volatile("cp.async.wait_group %0;" :: "n"(n))

// ===========================================================================
// Kernel 0: fp32 -> bf16 hi/lo split (8 elems / thread)
// ===========================================================================
__global__ void __launch_bounds__(256) cvt_kernel(
    const float* __restrict__ src, __nv_bfloat16* __restrict__ hi,
    __nv_bfloat16* __restrict__ lo, size_t n8)
{
    const size_t i = (size_t)blockIdx.x * blockDim.x + threadIdx.x;
    if (i < n8) {
        const float4 v0 = __ldg((const float4*)(src + i * 8));
        const float4 v1 = __ldg((const float4*)(src + i * 8 + 4));
        uint4 h, l;
        split8(v0, v1, h, l);
        *(uint4*)(hi + i * 8) = h;
        *(uint4*)(lo + i * 8) = l;
    }
}

// ===========================================================================
// Kernel A: proj via cp.async 3-stage pipeline, BK=64, preconverted bf16 in.
// Stage (64KB): Ahi 16K | Alo 16K | Bhi 16K | Blo 16K. 3 stages = 192KB.
// Tile rows 128 x 64k bf16 = 128B/row = 8 x 16B groups, XOR-swizzled.
// ===========================================================================
#define PJ_STAGE 65536
#define PJ_SMEM  (3 * PJ_STAGE)

__global__ void __launch_bounds__(256, 1) proj_mma_kernel(
    const float* __restrict__ B0, const float* __restrict__ B1,
    const float* __restrict__ B2, const float* __restrict__ B3)
{
    extern __shared__ __align__(16) char smp[];
    const uint32_t sbase = smem_u32(smp);

    const int tid  = threadIdx.x;
    const int wid  = tid >> 5;
    const int lane = tid & 31;
    const int wm   = wid & 3;
    const int wn   = wid >> 2;

    const int bx = blockIdx.x;         // 0..7 : 128-row slab of the 1024 outputs
    const int m0 = blockIdx.y * 128;
    const int wsel = bx >> 1;
    const float* bia = ((wsel == 0) ? B0 : (wsel == 1) ? B1 : (wsel == 2) ? B2 : B3)
                       + (bx & 1) * 128;

    float acc[2][8][4];
#pragma unroll
    for (int i = 0; i < 2; ++i)
#pragma unroll
        for (int j = 0; j < 8; ++j)
#pragma unroll
            for (int q = 0; q < 4; ++q) acc[i][j][q] = 0.0f;

    const int a_row = lane & 15;
    const int a_gh  = lane >> 4;
    const int b_nof = (lane & 7) + ((lane & 16) ? 8 : 0);
    const int b_gh  = (lane >> 3) & 1;

    auto issue = [&](int c, int buf) {
        const uint32_t sb = sbase + buf * PJ_STAGE;
#pragma unroll
        for (int it = 0; it < 4; ++it) {
            const int gi  = tid + it * 256;       // 0..1023
            const int row = gi >> 3;
            const int g   = gi & 7;
            const uint32_t o = row * 128 + ((g ^ (row & 7)) << 4);
            const size_t ax = (size_t)(m0 + row) * 256 + c * 64 + g * 8;
            const size_t bxo = (size_t)(bx * 128 + row) * 256 + c * 64 + g * 8;
            CP_A16(sb + o,         (const char*)(g_Xhi + ax));
            CP_A16(sb + 16384 + o, (const char*)(g_Xlo + ax));
            CP_A16(sb + 32768 + o, (const char*)(g_Whi + bxo));
            CP_A16(sb + 49152 + o, (const char*)(g_Wlo + bxo));
        }
        CP_COMMIT();
    };

    auto compute = [&](int buf) {
        const uint32_t sA  = sbase + buf * PJ_STAGE;
        const uint32_t sAl = sA + 16384;
        const uint32_t sB  = sA + 32768;
        const uint32_t sBl = sA + 49152;
#pragma unroll
        for (int ks = 0; ks < 4; ++ks) {
            uint32_t ah[2][4], al[2][4];
#pragma unroll
            for (int im = 0; im < 2; ++im) {
                const int row = wm * 32 + im * 16 + a_row;
                const int g   = ks * 2 + a_gh;
                const uint32_t o = row * 128 + ((g ^ (row & 7)) << 4);
                ldmatrix_x4(ah[im], sA + o);
                ldmatrix_x4(al[im], sAl + o);
            }
            uint32_t bh[4][4], bl[4][4];
#pragma unroll
            for (int bp = 0; bp < 4; ++bp) {
                const int row = wn * 64 + bp * 16 + b_nof;
                const int g   = ks * 2 + b_gh;
                const uint32_t o = row * 128 + ((g ^ (row & 7)) << 4);
                ldmatrix_x4(bh[bp], sB + o);
                ldmatrix_x4(bl[bp], sBl + o);
            }
#pragma unroll
            for (int im = 0; im < 2; ++im)
#pragma unroll
                for (int in = 0; in < 8; ++in) {
                    const uint32_t* Bh = &bh[in >> 1][(in & 1) * 2];
                    const uint32_t* Bl = &bl[in >> 1][(in & 1) * 2];
                    mma_bf16(acc[im][in], ah[im], Bh);
                    mma_bf16(acc[im][in], ah[im], Bl);
                    mma_bf16(acc[im][in], al[im], Bh);
                }
        }
    };

    issue(0, 0);
    issue(1, 1);
    issue(2, 2);

    CP_WAIT(2); __syncthreads();
    compute(0);
    __syncthreads();
    issue(3, 0);

    CP_WAIT(2); __syncthreads();
    compute(1);

    CP_WAIT(1); __syncthreads();
    compute(2);

    CP_WAIT(0); __syncthreads();
    compute(0);

    // ---- epilogue: bx 0,1 -> g_S0 fp32; bx>=2 -> g_Shi/g_Slo bf16 hi/lo
    const int r  = lane >> 2;
    const int cc = (lane & 3) * 2;
#pragma unroll
    for (int im = 0; im < 2; ++im) {
        const int mr = m0 + wm * 32 + im * 16 + r;
#pragma unroll
        for (int in = 0; in < 8; ++in) {
            const int ncol = wn * 64 + in * 8 + cc;
            const float2 bv = __ldg((const float2*)(bia + ncol));
            const float v00 = acc[im][in][0] + bv.x, v01 = acc[im][in][1] + bv.y;
            const float v10 = acc[im][in][2] + bv.x, v11 = acc[im][in][3] + bv.y;
            if (bx < 2) {
                *(float2*)&g_S0[(size_t)mr * 256 + bx * 128 + ncol]       = make_float2(v00, v01);
                *(float2*)&g_S0[(size_t)(mr + 8) * 256 + bx * 128 + ncol] = make_float2(v10, v11);
            } else {
                const int c3 = (bx - 2) * 128 + ncol;
                __nv_bfloat162 h0 = __floats2bfloat162_rn(v00, v01);
                float2 f0 = __bfloat1622float2(h0);
                __nv_bfloat162 l0 = __floats2bfloat162_rn(v00 - f0.x, v01 - f0.y);
                __nv_bfloat162 h1 = __floats2bfloat162_rn(v10, v11);
                float2 f1 = __bfloat1622float2(h1);
                __nv_bfloat162 l1 = __floats2bfloat162_rn(v10 - f1.x, v11 - f1.y);
                *(uint32_t*)&g_Shi[(size_t)mr * 768 + c3]       = b2u(h0);
                *(uint32_t*)&g_Slo[(size_t)mr * 768 + c3]       = b2u(l0);
                *(uint32_t*)&g_Shi[(size_t)(mr + 8) * 768 + c3] = b2u(h1);
                *(uint32_t*)&g_Slo[(size_t)(mr + 8) * 768 + c3] = b2u(l1);
            }
        }
    }
}

// ===========================================================================
// Kernel B (mma.sync attention) with n-aware tile skipping (nks16 in {112,128,16}).
// ===========================================================================
#define AT_SCORES 131072
#define AT_SP     193024
#define AT_SMEM   225792

__global__ void __launch_bounds__(256, 1) attn_mma_kernel(float* __restrict__ out)
{
    extern __shared__ __align__(16) char smp[];
    const uint32_t sQhi = smem_u32(smp);
    const uint32_t sQlo = sQhi + 32768;
    const uint32_t sKhi = sQhi + 65536;
    const uint32_t sKlo = sQhi + 98304;
    const uint32_t sVhi = sQhi;            // phase3 alias
    const uint32_t sVlo = sQhi + 65536;
    float* sscore = (float*)(smp + AT_SCORES);
    const uint32_t sP = sQhi + AT_SP;

    const int seg = blockIdx.x;
    const int b   = blockIdx.y;
    const int n   = (seg == 0) ? 103 : (seg == 1) ? 119 : 11;
    const int off = (seg == 0) ? 0   : (seg == 1) ? 103 : 222;
    const size_t grow0 = (size_t)b * SEQ + off;
    const int nks16 = ((n + 15) >> 4) << 4;      // 112 / 128 / 16
    const int nkt   = nks16 >> 4;

    const int tid  = threadIdx.x;
    const int wid  = tid >> 5;
    const int lane = tid & 31;
    const int wm   = wid & 3;
    const int wn   = wid >> 2;

    const int a_row = lane & 15;
    const int a_gh  = lane >> 4;
    const int b_nof = (lane & 7) + ((lane & 16) ? 8 : 0);
    const int b_gh  = (lane >> 3) & 1;

    const bool act_a[2] = { (wm * 32)      < nks16,
                            (wm * 32 + 16) < nks16 };
    bool act_b[4];
#pragma unroll
    for (int bp = 0; bp < 4; ++bp) act_b[bp] = (wn * 64 + bp * 16) < nks16;

    float acc[2][8][4];
#pragma unroll
    for (int i = 0; i < 2; ++i)
#pragma unroll
        for (int j = 0; j < 8; ++j)
#pragma unroll
            for (int q = 0; q < 4; ++q) acc[i][j][q] = 0.0f;

    // ============ phase 1: scores = s1 . s2^T (3-pass hi/lo), 2 K-chunks
#pragma unroll 1
    for (int kc = 0; kc < 2; ++kc) {
        if (kc) __syncthreads();
#pragma unroll
        for (int it = 0; it < 8; ++it) {
            const int gi = tid + it * 256;
            const int row = gi >> 4, g = gi & 15;
            const size_t src = (grow0 + row) * 768 + kc * 128 + g * 8;
            uint4 vh = make_uint4(0,0,0,0), vl = make_uint4(0,0,0,0);
            if (row < n) { vh = *(const uint4*)&g_Shi[src]; vl = *(const uint4*)&g_Slo[src]; }
            const uint32_t o = row * 256 + ((g ^ (row & 7)) << 4);
            *(uint4*)(smp + o)         = vh;
            *(uint4*)(smp + 32768 + o) = vl;
        }
#pragma unroll
        for (int it = 0; it < 8; ++it) {
            const int gi = tid + it * 256;
            const int row = gi >> 4, g = gi & 15;
            const size_t src = (grow0 + row) * 768 + 256 + kc * 128 + g * 8;
            uint4 vh = make_uint4(0,0,0,0), vl = make_uint4(0,0,0,0);
            if (row < n) { vh = *(const uint4*)&g_Shi[src]; vl = *(const uint4*)&g_Slo[src]; }
            const uint32_t o = row * 256 + ((g ^ (row & 7)) << 4);
            *(uint4*)(smp + 65536 + o) = vh;
            *(uint4*)(smp + 98304 + o) = vl;
        }
        __syncthreads();

#pragma unroll
        for (int ks = 0; ks < 8; ++ks) {
            uint32_t ah[2][4], al[2][4];
#pragma unroll
            for (int im = 0; im < 2; ++im) {
                if (!act_a[im]) continue;
                const int row = wm * 32 + im * 16 + a_row;
                const int g   = ks * 2 + a_gh;
                const uint32_t o = row * 256 + ((g ^ (row & 7)) << 4);
                ldmatrix_x4(ah[im], sQhi + o);
                ldmatrix_x4(al[im], sQlo + o);
            }
            uint32_t bh[4][4], bl[4][4];
#pragma unroll
            for (int bp = 0; bp < 4; ++bp) {
                if (!act_b[bp]) continue;
                const int row = wn * 64 + bp * 16 + b_nof;
                const int g   = ks * 2 + b_gh;
                const uint32_t o = row * 256 + ((g ^ (row & 7)) << 4);
                ldmatrix_x4(bh[bp], sKhi + o);
                ldmatrix_x4(bl[bp], sKlo + o);
            }
#pragma unroll
            for (int im = 0; im < 2; ++im)
#pragma unroll
                for (int in = 0; in < 8; ++in) {
                    if (!act_a[im] || !act_b[in >> 1]) continue;
                    const uint32_t* Bh = &bh[in >> 1][(in & 1) * 2];
                    const uint32_t* Bl = &bl[in >> 1][(in & 1) * 2];
                    mma_bf16(acc[im][in], ah[im], Bh);
                    mma_bf16(acc[im][in], ah[im], Bl);
                    mma_bf16(acc[im][in], al[im], Bh);
                }
        }
        __syncthreads();
    }

    // ============ phase 2: scale + mask -> scores SMEM -> softmax -> sP bf16
    {
        const int r  = lane >> 2;
        const int cc = (lane & 3) * 2;
#pragma unroll
        for (int im = 0; im < 2; ++im) {
            const int g1 = wm * 32 + im * 16 + r;
            const int g2 = g1 + 8;
#pragma unroll
            for (int in = 0; in < 8; ++in) {
                if (!act_b[in >> 1]) continue;
                const int col = wn * 64 + in * 8 + cc;
                if (g1 < n) {
                    float vx = (col     >= n) ? NEG : acc[im][in][0] * SCALE + ((col     == g1) ? NEG : 0.f);
                    float vy = (col + 1 >= n) ? NEG : acc[im][in][1] * SCALE + ((col + 1 == g1) ? NEG : 0.f);
                    sscore[g1 * 129 + col]     = vx;
                    sscore[g1 * 129 + col + 1] = vy;
                }
                if (g2 < n) {
                    float vx = (col     >= n) ? NEG : acc[im][in][2] * SCALE + ((col     == g2) ? NEG : 0.f);
                    float vy = (col + 1 >= n) ? NEG : acc[im][in][3] * SCALE + ((col + 1 == g2) ? NEG : 0.f);
                    sscore[g2 * 129 + col]     = vx;
                    sscore[g2 * 129 + col + 1] = vy;
                }
            }
        }
    }
    __syncthreads();

    // softmax: 8 warps x 16 rows, over nks16 cols
#pragma unroll 1
    for (int rr = 0; rr < 16; ++rr) {
        const int gi = rr * 8 + wid;
        if (gi < n) {
            float* rowp = &sscore[gi * 129];
            float mx = -1e30f;
            for (int j = lane; j < nks16; j += 32) mx = fmaxf(mx, rowp[j]);
#pragma unroll
            for (int o = 16; o; o >>= 1) mx = fmaxf(mx, __shfl_xor_sync(0xffffffffu, mx, o));
            float ssum = 0.f;
            for (int j = lane; j < nks16; j += 32) {
                const float e = __expf(rowp[j] - mx);
                rowp[j] = e;
                ssum += e;
            }
#pragma unroll
            for (int o = 16; o; o >>= 1) ssum += __shfl_xor_sync(0xffffffffu, ssum, o);
            const float inv = 1.0f / ssum;
            for (int j = lane; j < nks16; j += 32) rowp[j] *= inv;
        }
    }
    __syncthreads();

    // ============ load V (s3) + convert probs -> sP
#pragma unroll
    for (int it = 0; it < 16; ++it) {
        const int gi = tid + it * 256;
        const int j = gi >> 5, gg = gi & 31;
        const size_t src = (grow0 + j) * 768 + 512 + gg * 8;
        uint4 vh = make_uint4(0,0,0,0), vl = make_uint4(0,0,0,0);
        if (j < n) { vh = *(const uint4*)&g_Shi[src]; vl = *(const uint4*)&g_Slo[src]; }
        const uint32_t o = j * 512 + ((gg ^ (j & 7)) << 4);
        *(uint4*)(smp + o)         = vh;
        *(uint4*)(smp + 65536 + o) = vl;
    }
#pragma unroll
    for (int it = 0; it < 8; ++it) {
        const int gi = tid + it * 256;
        const int row = gi >> 4, g = gi & 15;
        uint4 v = make_uint4(0, 0, 0, 0);
        if (row < n && g * 8 < nks16) {
            const float* rp = &sscore[row * 129 + g * 8];
            v.x = b2u(__floats2bfloat162_rn(rp[0], rp[1]));
            v.y = b2u(__floats2bfloat162_rn(rp[2], rp[3]));
            v.z = b2u(__floats2bfloat162_rn(rp[4], rp[5]));
            v.w = b2u(__floats2bfloat162_rn(rp[6], rp[7]));
        }
        *(uint4*)(smp + AT_SP + row * 256 + ((g ^ (row & 7)) << 4)) = v;
    }
    __syncthreads();

    // ============ phase 3: out = s0 - probs @ s3, two 128-col halves
#pragma unroll 1
    for (int hb = 0; hb < 2; ++hb) {
        float acc2[2][8][4];
#pragma unroll
        for (int i = 0; i < 2; ++i)
#pragma unroll
            for (int j = 0; j < 8; ++j)
#pragma unroll
                for (int q = 0; q < 4; ++q) acc2[i][j][q] = 0.0f;

#pragma unroll 1
        for (int ks = 0; ks < nkt; ++ks) {
            uint32_t ap[2][4];
#pragma unroll
            for (int im = 0; im < 2; ++im) {
                if (!act_a[im]) continue;
                const int row = wm * 32 + im * 16 + a_row;
                const int g   = ks * 2 + a_gh;
                ldmatrix_x4(ap[im], sP + row * 256 + ((g ^ (row & 7)) << 4));
            }
            uint32_t bvh[4][4], bvl[4][4];
#pragma unroll
            for (int bp = 0; bp < 4; ++bp) {
                const int jrow = ks * 16 + (lane & 15);
                const int gg   = hb * 16 + wn * 8 + bp * 2 + (lane >> 4);
                const uint32_t o = jrow * 512 + ((gg ^ (jrow & 7)) << 4);
                ldmatrix_x4_t(bvh[bp], sVhi + o);
                ldmatrix_x4_t(bvl[bp], sVlo + o);
            }
#pragma unroll
            for (int im = 0; im < 2; ++im) {
                if (!act_a[im]) continue;
#pragma unroll
                for (int in = 0; in < 8; ++in) {
                    const uint32_t* Bh = &bvh[in >> 1][(in & 1) * 2];
                    const uint32_t* Bl = &bvl[in >> 1][(in & 1) * 2];
                    mma_bf16(acc2[im][in], ap[im], Bh);
                    mma_bf16(acc2[im][in], ap[im], Bl);
                }
            }
        }

        const int r  = lane >> 2;
        const int cc = (lane & 3) * 2;
#pragma unroll
        for (int im = 0; im < 2; ++im) {
            const int g1 = wm * 32 + im * 16 + r;
#pragma unroll
            for (int in = 0; in < 8; ++in) {
                const int h = hb * 128 + wn * 64 + in * 8 + cc;
                if (g1 < n) {
                    const float2 s0 = __ldg((const float2*)&g_S0[(grow0 + g1) * 256 + h]);
                    *(float2*)&out[(grow0 + g1) * 256 + h] =
                        make_float2(s0.x - acc2[im][in][0], s0.y - acc2[im][in][1]);
                }
                const int g2 = g1 + 8;
                if (g2 < n) {
                    const float2 s0 = __ldg((const float2*)&g_S0[(grow0 + g2) * 256 + h]);
                    *(float2*)&out[(grow0 + g2) * 256 + h] =
                        make_float2(s0.x - acc2[im][in][2], s0.y - acc2[im][in][3]);
                }
            }
        }
    }
}

// ---------------------------------------------------------------------------
extern "C" void kernel_launch(void* const* d_in, const int* in_sizes, int n_in,
                              void* d_out, int out_size)
{
    const float* toks = (const float*)d_in[0];
    const float* W0   = (const float*)d_in[1];
    const float* b0   = (const float*)d_in[2];
    const float* W1   = (const float*)d_in[3];
    const float* b1   = (const float*)d_in[4];
    const float* W2   = (const float*)d_in[5];
    const float* b2   = (const float*)d_in[6];
    const float* W3   = (const float*)d_in[7];
    const float* b3   = (const float*)d_in[8];
    float* out = (float*)d_out;

    __nv_bfloat16 *xhi, *xlo, *whi, *wlo;
    cudaGetSymbolAddress((void**)&xhi, g_Xhi);
    cudaGetSymbolAddress((void**)&xlo, g_Xlo);
    cudaGetSymbolAddress((void**)&whi, g_Whi);
    cudaGetSymbolAddress((void**)&wlo, g_Wlo);

    // Pre-convert X and W to bf16 hi/lo
    const size_t x8 = (size_t)MROWS * 256 / 8;          // 7,634,944
    cvt_kernel<<<(unsigned)((x8 + 255) / 256), 256>>>(toks, xhi, xlo, x8);
    const size_t w8 = 256 * 256 / 8;                    // 8192 per W
    cvt_kernel<<<32, 256>>>(W0, whi,             wlo,             w8);
    cvt_kernel<<<32, 256>>>(W1, whi + 256 * 256, wlo + 256 * 256, w8);
    cvt_kernel<<<32, 256>>>(W2, whi + 512 * 256, wlo + 512 * 256, w8);
    cvt_kernel<<<32, 256>>>(W3, whi + 768 * 256, wlo + 768 * 256, w8);

    cudaFuncSetAttribute(proj_mma_kernel,
                         cudaFuncAttributeMaxDynamicSharedMemorySize, PJ_SMEM);
    dim3 gA(8, MROWS / 128);
    proj_mma_kernel<<<gA, 256, PJ_SMEM>>>(b0, b1, b2, b3);

    cudaFuncSetAttribute(attn_mma_kernel,
                         cudaFuncAttributeMaxDynamicSharedMemorySize, AT_SMEM);
    dim3 gB(3, BATCH);
    attn_mma_kernel<<<gB, 256, AT_SMEM>>>(out);
}

// round 8
// speedup vs baseline: 2.8353x; 1.3596x over previous
#include <cuda_runtime.h>
#include <cuda_fp16.h>
#include <cstdint>
#include <math.h>

#define HIDDEN 256
#define SEQ    233
#define BATCH  1024
#define MROWS  (BATCH * SEQ)          // 238592 = 128 * 1864
#define SCALE  0.0625f                // 1/sqrt(256)
#define NEG    (-10000.0f)

// Scratch buffers (fp16 path)
static __device__ float   g_S0 [(size_t)MROWS * 256];   // s0 fp32
static __device__ __half  g_Shi[(size_t)MROWS * 768];   // s1|s2|s3 fp16 hi
static __device__ __half  g_Slo[(size_t)MROWS * 256];   // s1 fp16 lo only
static __device__ __half  g_Xhi[(size_t)MROWS * 256];
static __device__ __half  g_Xlo[(size_t)MROWS * 256];
static __device__ __half  g_Whi[1024 * 256];

__device__ __forceinline__ uint32_t smem_u32(const void* p) {
    uint32_t a;
    asm("{ .reg .u64 t; cvta.to.shared.u64 t, %1; cvt.u32.u64 %0, t; }" : "=r"(a) : "l"(p));
    return a;
}
__device__ __forceinline__ uint32_t h2u(__half2 h) {
    return *reinterpret_cast<uint32_t*>(&h);
}
__device__ __forceinline__ void ldmatrix_x4(uint32_t* r, uint32_t addr) {
    asm volatile("ldmatrix.sync.aligned.m8n8.x4.shared.b16 {%0,%1,%2,%3}, [%4];"
                 : "=r"(r[0]), "=r"(r[1]), "=r"(r[2]), "=r"(r[3]) : "r"(addr));
}
__device__ __forceinline__ void ldmatrix_x4_t(uint32_t* r, uint32_t addr) {
    asm volatile("ldmatrix.sync.aligned.m8n8.x4.trans.shared.b16 {%0,%1,%2,%3}, [%4];"
                 : "=r"(r[0]), "=r"(r[1]), "=r"(r[2]), "=r"(r[3]) : "r"(addr));
}
__device__ __forceinline__ void mma_f16(float* c, const uint32_t* a, const uint32_t* b) {
    asm volatile(
        "mma.sync.aligned.m16n8k16.row.col.f32.f16.f16.f32 "
        "{%0,%1,%2,%3}, {%4,%5,%6,%7}, {%8,%9}, {%0,%1,%2,%3};"
        : "+f"(c[0]), "+f"(c[1]), "+f"(c[2]), "+f"(c[3])
        : "r"(a[0]), "r"(a[1]), "r"(a[2]), "r"(a[3]), "r"(b[0]), "r"(b[1]));
}
__device__ __forceinline__ void split8h(const float4 v0, const float4 v1,
                                        uint4& hi, uint4& lo) {
    __half2 h0 = __floats2half2_rn(v0.x, v0.y);
    __half2 h1 = __floats2half2_rn(v0.z, v0.w);
    __half2 h2 = __floats2half2_rn(v1.x, v1.y);
    __half2 h3 = __floats2half2_rn(v1.z, v1.w);
    float2 f0 = __half22float2(h0), f1 = __half22float2(h1);
    float2 f2 = __half22float2(h2), f3 = __half22float2(h3);
    __half2 l0 = __floats2half2_rn(v0.x - f0.x, v0.y - f0.y);
    __half2 l1 = __floats2half2_rn(v0.z - f1.x, v0.w - f1.y);
    __half2 l2 = __floats2half2_rn(v1.x - f2.x, v1.y - f2.y);
    __half2 l3 = __floats2half2_rn(v1.z - f3.x, v1.w - f3.y);
    hi = make_uint4(h2u(h0), h2u(h1), h2u(h2), h2u(h3));
    lo = make_uint4(h2u(l0), h2u(l1), h2u(l2), h2u(l3));
}

#define CP_A16(dst, src) asm volatile("cp.async.cg.shared.global [%0], [%1], 16;" :: "r"(dst), "l"(src))
#define CP_COMMIT()      asm volatile("cp.async.commit_group;")
#define CP_WAIT(n)       asm volatile("cp.async.wait_group %0;" :: "n"(n))

// ===========================================================================
// Converters
// ===========================================================================
__global__ void __launch_bounds__(256) cvt_kernel(
    const float* __restrict__ src, __half* __restrict__ hi,
    __half* __restrict__ lo, size_t n8)
{
    const size_t i = (size_t)blockIdx.x * blockDim.x + threadIdx.x;
    if (i < n8) {
        const float4 v0 = __ldg((const float4*)(src + i * 8));
        const float4 v1 = __ldg((const float4*)(src + i * 8 + 4));
        uint4 h, l;
        split8h(v0, v1, h, l);
        *(uint4*)(hi + i * 8) = h;
        *(uint4*)(lo + i * 8) = l;
    }
}
__global__ void __launch_bounds__(256) cvt_hi_kernel(
    const float* __restrict__ src, __half* __restrict__ hi, size_t n8)
{
    const size_t i = (size_t)blockIdx.x * blockDim.x + threadIdx.x;
    if (i < n8) {
        const float4 v0 = __ldg((const float4*)(src + i * 8));
        const float4 v1 = __ldg((const float4*)(src + i * 8 + 4));
        uint4 h;
        h.x = h2u(__floats2half2_rn(v0.x, v0.y));
        h.y = h2u(__floats2half2_rn(v0.z, v0.w));
        h.z = h2u(__floats2half2_rn(v1.x, v1.y));
        h.w = h2u(__floats2half2_rn(v1.z, v1.w));
        *(uint4*)(hi + i * 8) = h;
    }
}

// ===========================================================================
// Kernel A: proj, fp16 2-pass (x·whi), cp.async 3-stage pipeline, BK=64.
// Stage (48KB): Ahi 16K | Alo 16K | Bhi 16K.
// ===========================================================================
#define PJ_STAGE 49152
#define PJ_SMEM  (3 * PJ_STAGE)

__global__ void __launch_bounds__(256, 1) proj_mma_kernel(
    const float* __restrict__ B0, const float* __restrict__ B1,
    const float* __restrict__ B2, const float* __restrict__ B3)
{
    extern __shared__ __align__(16) char smp[];
    const uint32_t sbase = smem_u32(smp);

    const int tid  = threadIdx.x;
    const int wid  = tid >> 5;
    const int lane = tid & 31;
    const int wm   = wid & 3;
    const int wn   = wid >> 2;

    const int bx = blockIdx.x;         // 0..7 : 128-row slab of the 1024 outputs
    const int m0 = blockIdx.y * 128;
    const int wsel = bx >> 1;
    const float* bia = ((wsel == 0) ? B0 : (wsel == 1) ? B1 : (wsel == 2) ? B2 : B3)
                       + (bx & 1) * 128;

    float acc[2][8][4];
#pragma unroll
    for (int i = 0; i < 2; ++i)
#pragma unroll
        for (int j = 0; j < 8; ++j)
#pragma unroll
            for (int q = 0; q < 4; ++q) acc[i][j][q] = 0.0f;

    const int a_row = lane & 15;
    const int a_gh  = lane >> 4;
    const int b_nof = (lane & 7) + ((lane & 16) ? 8 : 0);
    const int b_gh  = (lane >> 3) & 1;

    auto issue = [&](int c, int buf) {
        const uint32_t sb = sbase + buf * PJ_STAGE;
#pragma unroll
        for (int it = 0; it < 4; ++it) {
            const int gi  = tid + it * 256;       // 0..1023
            const int row = gi >> 3;
            const int g   = gi & 7;
            const uint32_t o = row * 128 + ((g ^ (row & 7)) << 4);
            const size_t ax  = (size_t)(m0 + row) * 256 + c * 64 + g * 8;
            const size_t bxo = (size_t)(bx * 128 + row) * 256 + c * 64 + g * 8;
            CP_A16(sb + o,         (const char*)(g_Xhi + ax));
            CP_A16(sb + 16384 + o, (const char*)(g_Xlo + ax));
            CP_A16(sb + 32768 + o, (const char*)(g_Whi + bxo));
        }
        CP_COMMIT();
    };

    auto compute = [&](int buf) {
        const uint32_t sA  = sbase + buf * PJ_STAGE;
        const uint32_t sAl = sA + 16384;
        const uint32_t sB  = sA + 32768;
#pragma unroll
        for (int ks = 0; ks < 4; ++ks) {
            uint32_t ah[2][4], al[2][4];
#pragma unroll
            for (int im = 0; im < 2; ++im) {
                const int row = wm * 32 + im * 16 + a_row;
                const int g   = ks * 2 + a_gh;
                const uint32_t o = row * 128 + ((g ^ (row & 7)) << 4);
                ldmatrix_x4(ah[im], sA + o);
                ldmatrix_x4(al[im], sAl + o);
            }
            uint32_t bh[4][4];
#pragma unroll
            for (int bp = 0; bp < 4; ++bp) {
                const int row = wn * 64 + bp * 16 + b_nof;
                const int g   = ks * 2 + b_gh;
                const uint32_t o = row * 128 + ((g ^ (row & 7)) << 4);
                ldmatrix_x4(bh[bp], sB + o);
            }
#pragma unroll
            for (int im = 0; im < 2; ++im)
#pragma unroll
                for (int in = 0; in < 8; ++in) {
                    const uint32_t* Bh = &bh[in >> 1][(in & 1) * 2];
                    mma_f16(acc[im][in], ah[im], Bh);
                    mma_f16(acc[im][in], al[im], Bh);
                }
        }
    };

    issue(0, 0);
    issue(1, 1);
    issue(2, 2);

    CP_WAIT(2); __syncthreads();
    compute(0);
    __syncthreads();
    issue(3, 0);

    CP_WAIT(2); __syncthreads();
    compute(1);

    CP_WAIT(1); __syncthreads();
    compute(2);

    CP_WAIT(0); __syncthreads();
    compute(0);

    // ---- epilogue: bx 0,1 -> g_S0 fp32; bx 2,3 -> s1 hi+lo; bx 4..7 -> hi only
    const int r  = lane >> 2;
    const int cc = (lane & 3) * 2;
#pragma unroll
    for (int im = 0; im < 2; ++im) {
        const int mr = m0 + wm * 32 + im * 16 + r;
#pragma unroll
        for (int in = 0; in < 8; ++in) {
            const int ncol = wn * 64 + in * 8 + cc;
            const float2 bv = __ldg((const float2*)(bia + ncol));
            const float v00 = acc[im][in][0] + bv.x, v01 = acc[im][in][1] + bv.y;
            const float v10 = acc[im][in][2] + bv.x, v11 = acc[im][in][3] + bv.y;
            if (bx < 2) {
                *(float2*)&g_S0[(size_t)mr * 256 + bx * 128 + ncol]       = make_float2(v00, v01);
                *(float2*)&g_S0[(size_t)(mr + 8) * 256 + bx * 128 + ncol] = make_float2(v10, v11);
            } else {
                const int c3 = (bx - 2) * 128 + ncol;                 // 0..767
                __half2 h0 = __floats2half2_rn(v00, v01);
                __half2 h1 = __floats2half2_rn(v10, v11);
                *(uint32_t*)&g_Shi[(size_t)mr * 768 + c3]       = h2u(h0);
                *(uint32_t*)&g_Shi[(size_t)(mr + 8) * 768 + c3] = h2u(h1);
                if (bx < 4) {                                          // s1 lo
                    float2 f0 = __half22float2(h0);
                    float2 f1 = __half22float2(h1);
                    __half2 l0 = __floats2half2_rn(v00 - f0.x, v01 - f0.y);
                    __half2 l1 = __floats2half2_rn(v10 - f1.x, v11 - f1.y);
                    *(uint32_t*)&g_Slo[(size_t)mr * 256 + c3]       = h2u(l0);
                    *(uint32_t*)&g_Slo[(size_t)(mr + 8) * 256 + c3] = h2u(l1);
                }
            }
        }
    }
}

// ===========================================================================
// Kernel B: attention, fp16. Phase1 2-pass (s1hi+s1lo)·s2hi; phase3 1-pass
// probs_fp16 · s3hi. n-aware tile skipping.
// SMEM: ph1 Qhi[0,32K) Qlo[32K,64K) Khi[64K,96K); ph3 Vhi[0,64K)
//       sscore fp32 [120][129] @98304; sP fp16 [128][128] @163840. Total 192K.
// ===========================================================================
#define AT_SCORES 98304
#define AT_SP     163840
#define AT_SMEM   196608

__global__ void __launch_bounds__(256, 1) attn_mma_kernel(float* __restrict__ out)
{
    extern __shared__ __align__(16) char smp[];
    const uint32_t sQhi = smem_u32(smp);
    const uint32_t sQlo = sQhi + 32768;
    const uint32_t sKhi = sQhi + 65536;
    const uint32_t sVhi = sQhi;            // phase3 alias [128 j][256 h] fp16
    float* sscore = (float*)(smp + AT_SCORES);
    const uint32_t sP = sQhi + AT_SP;

    const int seg = blockIdx.x;
    const int b   = blockIdx.y;
    const int n   = (seg == 0) ? 103 : (seg == 1) ? 119 : 11;
    const int off = (seg == 0) ? 0   : (seg == 1) ? 103 : 222;
    const size_t grow0 = (size_t)b * SEQ + off;
    const int nks16 = ((n + 15) >> 4) << 4;      // 112 / 128 / 16
    const int nkt   = nks16 >> 4;

    const int tid  = threadIdx.x;
    const int wid  = tid >> 5;
    const int lane = tid & 31;
    const int wm   = wid & 3;
    const int wn   = wid >> 2;

    const int a_row = lane & 15;
    const int a_gh  = lane >> 4;
    const int b_nof = (lane & 7) + ((lane & 16) ? 8 : 0);
    const int b_gh  = (lane >> 3) & 1;

    const bool act_a[2] = { (wm * 32)      < nks16,
                            (wm * 32 + 16) < nks16 };
    bool act_b[4];
#pragma unroll
    for (int bp = 0; bp < 4; ++bp) act_b[bp] = (wn * 64 + bp * 16) < nks16;

    float acc[2][8][4];
#pragma unroll
    for (int i = 0; i < 2; ++i)
#pragma unroll
        for (int j = 0; j < 8; ++j)
#pragma unroll
            for (int q = 0; q < 4; ++q) acc[i][j][q] = 0.0f;

    // ============ phase 1: scores = s1 . s2hi^T (2-pass), 2 K-chunks
#pragma unroll 1
    for (int kc = 0; kc < 2; ++kc) {
        if (kc) __syncthreads();
#pragma unroll
        for (int it = 0; it < 8; ++it) {
            const int gi = tid + it * 256;
            const int row = gi >> 4, g = gi & 15;
            uint4 vh = make_uint4(0,0,0,0), vl = make_uint4(0,0,0,0);
            if (row < n) {
                vh = *(const uint4*)&g_Shi[(grow0 + row) * 768 + kc * 128 + g * 8];
                vl = *(const uint4*)&g_Slo[(grow0 + row) * 256 + kc * 128 + g * 8];
            }
            const uint32_t o = row * 256 + ((g ^ (row & 7)) << 4);
            *(uint4*)(smp + o)         = vh;
            *(uint4*)(smp + 32768 + o) = vl;
        }
#pragma unroll
        for (int it = 0; it < 8; ++it) {
            const int gi = tid + it * 256;
            const int row = gi >> 4, g = gi & 15;
            uint4 vh = make_uint4(0,0,0,0);
            if (row < n)
                vh = *(const uint4*)&g_Shi[(grow0 + row) * 768 + 256 + kc * 128 + g * 8];
            const uint32_t o = row * 256 + ((g ^ (row & 7)) << 4);
            *(uint4*)(smp + 65536 + o) = vh;
        }
        __syncthreads();

#pragma unroll
        for (int ks = 0; ks < 8; ++ks) {
            uint32_t ah[2][4], al[2][4];
#pragma unroll
            for (int im = 0; im < 2; ++im) {
                if (!act_a[im]) continue;
                const int row = wm * 32 + im * 16 + a_row;
                const int g   = ks * 2 + a_gh;
                const uint32_t o = row * 256 + ((g ^ (row & 7)) << 4);
                ldmatrix_x4(ah[im], sQhi + o);
                ldmatrix_x4(al[im], sQlo + o);
            }
            uint32_t bh[4][4];
#pragma unroll
            for (int bp = 0; bp < 4; ++bp) {
                if (!act_b[bp]) continue;
                const int row = wn * 64 + bp * 16 + b_nof;
                const int g   = ks * 2 + b_gh;
                const uint32_t o = row * 256 + ((g ^ (row & 7)) << 4);
                ldmatrix_x4(bh[bp], sKhi + o);
            }
#pragma unroll
            for (int im = 0; im < 2; ++im)
#pragma unroll
                for (int in = 0; in < 8; ++in) {
                    if (!act_a[im] || !act_b[in >> 1]) continue;
                    const uint32_t* Bh = &bh[in >> 1][(in & 1) * 2];
                    mma_f16(acc[im][in], ah[im], Bh);
                    mma_f16(acc[im][in], al[im], Bh);
                }
        }
        __syncthreads();
    }

    // ============ phase 2: scale + mask -> sscore -> softmax -> sP fp16
    {
        const int r  = lane >> 2;
        const int cc = (lane & 3) * 2;
#pragma unroll
        for (int im = 0; im < 2; ++im) {
            const int g1 = wm * 32 + im * 16 + r;
            const int g2 = g1 + 8;
#pragma unroll
            for (int in = 0; in < 8; ++in) {
                if (!act_b[in >> 1]) continue;
                const int col = wn * 64 + in * 8 + cc;
                if (g1 < n) {
                    float vx = (col     >= n) ? NEG : acc[im][in][0] * SCALE + ((col     == g1) ? NEG : 0.f);
                    float vy = (col + 1 >= n) ? NEG : acc[im][in][1] * SCALE + ((col + 1 == g1) ? NEG : 0.f);
                    sscore[g1 * 129 + col]     = vx;
                    sscore[g1 * 129 + col + 1] = vy;
                }
                if (g2 < n) {
                    float vx = (col     >= n) ? NEG : acc[im][in][2] * SCALE + ((col     == g2) ? NEG : 0.f);
                    float vy = (col + 1 >= n) ? NEG : acc[im][in][3] * SCALE + ((col + 1 == g2) ? NEG : 0.f);
                    sscore[g2 * 129 + col]     = vx;
                    sscore[g2 * 129 + col + 1] = vy;
                }
            }
        }
    }
    __syncthreads();

    // softmax: 8 warps x 16 rows, over nks16 cols
#pragma unroll 1
    for (int rr = 0; rr < 16; ++rr) {
        const int gi = rr * 8 + wid;
        if (gi < n) {
            float* rowp = &sscore[gi * 129];
            float mx = -1e30f;
            for (int j = lane; j < nks16; j += 32) mx = fmaxf(mx, rowp[j]);
#pragma unroll
            for (int o = 16; o; o >>= 1) mx = fmaxf(mx, __shfl_xor_sync(0xffffffffu, mx, o));
            float ssum = 0.f;
            for (int j = lane; j < nks16; j += 32) {
                const float e = __expf(rowp[j] - mx);
                rowp[j] = e;
                ssum += e;
            }
#pragma unroll
            for (int o = 16; o; o >>= 1) ssum += __shfl_xor_sync(0xffffffffu, ssum, o);
            const float inv = 1.0f / ssum;
            for (int j = lane; j < nks16; j += 32) rowp[j] *= inv;
        }
    }
    __syncthreads();

    // ============ load V hi (s3) + convert probs -> sP fp16
#pragma unroll
    for (int it = 0; it < 16; ++it) {
        const int gi = tid + it * 256;
        const int j = gi >> 5, gg = gi & 31;
        uint4 vh = make_uint4(0,0,0,0);
        if (j < n) vh = *(const uint4*)&g_Shi[(grow0 + j) * 768 + 512 + gg * 8];
        *(uint4*)(smp + j * 512 + ((gg ^ (j & 7)) << 4)) = vh;
    }
#pragma unroll
    for (int it = 0; it < 8; ++it) {
        const int gi = tid + it * 256;
        const int row = gi >> 4, g = gi & 15;
        uint4 v = make_uint4(0, 0, 0, 0);
        if (row < n && g * 8 < nks16) {
            const float* rp = &sscore[row * 129 + g * 8];
            v.x = h2u(__floats2half2_rn(rp[0], rp[1]));
            v.y = h2u(__floats2half2_rn(rp[2], rp[3]));
            v.z = h2u(__floats2half2_rn(rp[4], rp[5]));
            v.w = h2u(__floats2half2_rn(rp[6], rp[7]));
        }
        *(uint4*)(smp + AT_SP + row * 256 + ((g ^ (row & 7)) << 4)) = v;
    }
    __syncthreads();

    // ============ phase 3: out = s0 - probs @ s3hi (1-pass), two halves
#pragma unroll 1
    for (int hb = 0; hb < 2; ++hb) {
        float acc2[2][8][4];
#pragma unroll
        for (int i = 0; i < 2; ++i)
#pragma unroll
            for (int j = 0; j < 8; ++j)
#pragma unroll
                for (int q = 0; q < 4; ++q) acc2[i][j][q] = 0.0f;

#pragma unroll 1
        for (int ks = 0; ks < nkt; ++ks) {
            uint32_t ap[2][4];
#pragma unroll
            for (int im = 0; im < 2; ++im) {
                if (!act_a[im]) continue;
                const int row = wm * 32 + im * 16 + a_row;
                const int g   = ks * 2 + a_gh;
                ldmatrix_x4(ap[im], sP + row * 256 + ((g ^ (row & 7)) << 4));
            }
            uint32_t bvh[4][4];
#pragma unroll
            for (int bp = 0; bp < 4; ++bp) {
                const int jrow = ks * 16 + (lane & 15);
                const int gg   = hb * 16 + wn * 8 + bp * 2 + (lane >> 4);
                const uint32_t o = jrow * 512 + ((gg ^ (jrow & 7)) << 4);
                ldmatrix_x4_t(bvh[bp], sVhi + o);
            }
#pragma unroll
            for (int im = 0; im < 2; ++im) {
                if (!act_a[im]) continue;
#pragma unroll
                for (int in = 0; in < 8; ++in) {
                    const uint32_t* Bh = &bvh[in >> 1][(in & 1) * 2];
                    mma_f16(acc2[im][in], ap[im], Bh);
                }
            }
        }

        const int r  = lane >> 2;
        const int cc = (lane & 3) * 2;
#pragma unroll
        for (int im = 0; im < 2; ++im) {
            const int g1 = wm * 32 + im * 16 + r;
#pragma unroll
            for (int in = 0; in < 8; ++in) {
                const int h = hb * 128 + wn * 64 + in * 8 + cc;
                if (g1 < n) {
                    const float2 s0 = __ldg((const float2*)&g_S0[(grow0 + g1) * 256 + h]);
                    *(float2*)&out[(grow0 + g1) * 256 + h] =
                        make_float2(s0.x - acc2[im][in][0], s0.y - acc2[im][in][1]);
                }
                const int g2 = g1 + 8;
                if (g2 < n) {
                    const float2 s0 = __ldg((const float2*)&g_S0[(grow0 + g2) * 256 + h]);
                    *(float2*)&out[(grow0 + g2) * 256 + h] =
                        make_float2(s0.x - acc2[im][in][2], s0.y - acc2[im][in][3]);
                }
            }
        }
    }
}

// ---------------------------------------------------------------------------
extern "C" void kernel_launch(void* const* d_in, const int* in_sizes, int n_in,
                              void* d_out, int out_size)
{
    const float* toks = (const float*)d_in[0];
    const float* W0   = (const float*)d_in[1];
    const float* b0   = (const float*)d_in[2];
    const float* W1   = (const float*)d_in[3];
    const float* b1   = (const float*)d_in[4];
    const float* W2   = (const float*)d_in[5];
    const float* b2   = (const float*)d_in[6];
    const float* W3   = (const float*)d_in[7];
    const float* b3   = (const float*)d_in[8];
    float* out = (float*)d_out;

    __half *xhi, *xlo, *whi;
    cudaGetSymbolAddress((void**)&xhi, g_Xhi);
    cudaGetSymbolAddress((void**)&xlo, g_Xlo);
    cudaGetSymbolAddress((void**)&whi, g_Whi);

    const size_t x8 = (size_t)MROWS * 256 / 8;
    cvt_kernel<<<(unsigned)((x8 + 255) / 256), 256>>>(toks, xhi, xlo, x8);
    const size_t w8 = 256 * 256 / 8;
    cvt_hi_kernel<<<32, 256>>>(W0, whi,             w8);
    cvt_hi_kernel<<<32, 256>>>(W1, whi + 256 * 256, w8);
    cvt_hi_kernel<<<32, 256>>>(W2, whi + 512 * 256, w8);
    cvt_hi_kernel<<<32, 256>>>(W3, whi + 768 * 256, w8);

    cudaFuncSetAttribute(proj_mma_kernel,
                         cudaFuncAttributeMaxDynamicSharedMemorySize, PJ_SMEM);
    dim3 gA(8, MROWS / 128);
    proj_mma_kernel<<<gA, 256, PJ_SMEM>>>(b0, b1, b2, b3);

    cudaFuncSetAttribute(attn_mma_kernel,
                         cudaFuncAttributeMaxDynamicSharedMemorySize, AT_SMEM);
    dim3 gB(3, BATCH);
    attn_mma_kernel<<<gB, 256, AT_SMEM>>>(out);
}

// round 9
// speedup vs baseline: 3.2193x; 1.1355x over previous
#include <cuda_runtime.h>
#include <cuda_fp16.h>
#include <cstdint>
#include <math.h>

#define HIDDEN 256
#define SEQ    233
#define BATCH  1024
#define MROWS  (BATCH * SEQ)          // 238592 = 128 * 1864
#define SCALE  0.0625f                // 1/sqrt(256)
#define NEG    (-10000.0f)

// Scratch buffers (fp16 path)
static __device__ float   g_S0 [(size_t)MROWS * 256];   // s0 fp32
static __device__ __half  g_Shi[(size_t)MROWS * 768];   // s1|s2|s3 fp16
static __device__ __half  g_Xhi[(size_t)MROWS * 256];
static __device__ __half  g_Xlo[(size_t)MROWS * 256];
static __device__ __half  g_Whi[1024 * 256];

__device__ __forceinline__ uint32_t smem_u32(const void* p) {
    uint32_t a;
    asm("{ .reg .u64 t; cvta.to.shared.u64 t, %1; cvt.u32.u64 %0, t; }" : "=r"(a) : "l"(p));
    return a;
}
__device__ __forceinline__ uint32_t h2u(__half2 h) {
    return *reinterpret_cast<uint32_t*>(&h);
}
__device__ __forceinline__ void ldmatrix_x4(uint32_t* r, uint32_t addr) {
    asm volatile("ldmatrix.sync.aligned.m8n8.x4.shared.b16 {%0,%1,%2,%3}, [%4];"
                 : "=r"(r[0]), "=r"(r[1]), "=r"(r[2]), "=r"(r[3]) : "r"(addr));
}
__device__ __forceinline__ void ldmatrix_x4_t(uint32_t* r, uint32_t addr) {
    asm volatile("ldmatrix.sync.aligned.m8n8.x4.trans.shared.b16 {%0,%1,%2,%3}, [%4];"
                 : "=r"(r[0]), "=r"(r[1]), "=r"(r[2]), "=r"(r[3]) : "r"(addr));
}
__device__ __forceinline__ void mma_f16(float* c, const uint32_t* a, const uint32_t* b) {
    asm volatile(
        "mma.sync.aligned.m16n8k16.row.col.f32.f16.f16.f32 "
        "{%0,%1,%2,%3}, {%4,%5,%6,%7}, {%8,%9}, {%0,%1,%2,%3};"
        : "+f"(c[0]), "+f"(c[1]), "+f"(c[2]), "+f"(c[3])
        : "r"(a[0]), "r"(a[1]), "r"(a[2]), "r"(a[3]), "r"(b[0]), "r"(b[1]));
}
__device__ __forceinline__ void split8h(const float4 v0, const float4 v1,
                                        uint4& hi, uint4& lo) {
    __half2 h0 = __floats2half2_rn(v0.x, v0.y);
    __half2 h1 = __floats2half2_rn(v0.z, v0.w);
    __half2 h2 = __floats2half2_rn(v1.x, v1.y);
    __half2 h3 = __floats2half2_rn(v1.z, v1.w);
    float2 f0 = __half22float2(h0), f1 = __half22float2(h1);
    float2 f2 = __half22float2(h2), f3 = __half22float2(h3);
    __half2 l0 = __floats2half2_rn(v0.x - f0.x, v0.y - f0.y);
    __half2 l1 = __floats2half2_rn(v0.z - f1.x, v0.w - f1.y);
    __half2 l2 = __floats2half2_rn(v1.x - f2.x, v1.y - f2.y);
    __half2 l3 = __floats2half2_rn(v1.z - f3.x, v1.w - f3.y);
    hi = make_uint4(h2u(h0), h2u(h1), h2u(h2), h2u(h3));
    lo = make_uint4(h2u(l0), h2u(l1), h2u(l2), h2u(l3));
}

#define CP_A16(dst, src) asm volatile("cp.async.cg.shared.global [%0], [%1], 16;" :: "r"(dst), "l"(src))
#define CP_COMMIT()      asm volatile("cp.async.commit_group;")
#define CP_WAIT(n)       asm volatile("cp.async.wait_group %0;" :: "n"(n))

// ===========================================================================
// Converters
// ===========================================================================
__global__ void __launch_bounds__(256) cvt_kernel(
    const float* __restrict__ src, __half* __restrict__ hi,
    __half* __restrict__ lo, size_t n8)
{
    const size_t i = (size_t)blockIdx.x * blockDim.x + threadIdx.x;
    if (i < n8) {
        const float4 v0 = __ldg((const float4*)(src + i * 8));
        const float4 v1 = __ldg((const float4*)(src + i * 8 + 4));
        uint4 h, l;
        split8h(v0, v1, h, l);
        *(uint4*)(hi + i * 8) = h;
        *(uint4*)(lo + i * 8) = l;
    }
}
__global__ void __launch_bounds__(256) cvt_hi_kernel(
    const float* __restrict__ src, __half* __restrict__ hi, size_t n8)
{
    const size_t i = (size_t)blockIdx.x * blockDim.x + threadIdx.x;
    if (i < n8) {
        const float4 v0 = __ldg((const float4*)(src + i * 8));
        const float4 v1 = __ldg((const float4*)(src + i * 8 + 4));
        uint4 h;
        h.x = h2u(__floats2half2_rn(v0.x, v0.y));
        h.y = h2u(__floats2half2_rn(v0.z, v0.w));
        h.z = h2u(__floats2half2_rn(v1.x, v1.y));
        h.w = h2u(__floats2half2_rn(v1.z, v1.w));
        *(uint4*)(hi + i * 8) = h;
    }
}

// ===========================================================================
// Kernel A: proj. bx<2 (s0 slab): 2-pass (xhi+xlo)·whi. bx>=2: 1-pass xhi·whi.
// cp.async 3-stage pipeline, BK=64. Stage (48KB): Ahi 16K | Alo 16K | Bhi 16K.
// ===========================================================================
#define PJ_STAGE 49152
#define PJ_SMEM  (3 * PJ_STAGE)

__global__ void __launch_bounds__(256, 1) proj_mma_kernel(
    const float* __restrict__ B0, const float* __restrict__ B1,
    const float* __restrict__ B2, const float* __restrict__ B3)
{
    extern __shared__ __align__(16) char smp[];
    const uint32_t sbase = smem_u32(smp);

    const int tid  = threadIdx.x;
    const int wid  = tid >> 5;
    const int lane = tid & 31;
    const int wm   = wid & 3;
    const int wn   = wid >> 2;

    const int bx = blockIdx.x;         // 0..7 : 128-row slab of the 1024 outputs
    const int m0 = blockIdx.y * 128;
    const int wsel = bx >> 1;
    const float* bia = ((wsel == 0) ? B0 : (wsel == 1) ? B1 : (wsel == 2) ? B2 : B3)
                       + (bx & 1) * 128;
    const bool two_pass = (bx < 2);    // s0 slab needs the xlo correction pass

    float acc[2][8][4];
#pragma unroll
    for (int i = 0; i < 2; ++i)
#pragma unroll
        for (int j = 0; j < 8; ++j)
#pragma unroll
            for (int q = 0; q < 4; ++q) acc[i][j][q] = 0.0f;

    const int a_row = lane & 15;
    const int a_gh  = lane >> 4;
    const int b_nof = (lane & 7) + ((lane & 16) ? 8 : 0);
    const int b_gh  = (lane >> 3) & 1;

    auto issue = [&](int c, int buf) {
        const uint32_t sb = sbase + buf * PJ_STAGE;
#pragma unroll
        for (int it = 0; it < 4; ++it) {
            const int gi  = tid + it * 256;       // 0..1023
            const int row = gi >> 3;
            const int g   = gi & 7;
            const uint32_t o = row * 128 + ((g ^ (row & 7)) << 4);
            const size_t ax  = (size_t)(m0 + row) * 256 + c * 64 + g * 8;
            const size_t bxo = (size_t)(bx * 128 + row) * 256 + c * 64 + g * 8;
            CP_A16(sb + o,         (const char*)(g_Xhi + ax));
            if (two_pass) CP_A16(sb + 16384 + o, (const char*)(g_Xlo + ax));
            CP_A16(sb + 32768 + o, (const char*)(g_Whi + bxo));
        }
        CP_COMMIT();
    };

    auto compute = [&](int buf) {
        const uint32_t sA  = sbase + buf * PJ_STAGE;
        const uint32_t sAl = sA + 16384;
        const uint32_t sB  = sA + 32768;
#pragma unroll
        for (int ks = 0; ks < 4; ++ks) {
            uint32_t ah[2][4], al[2][4];
#pragma unroll
            for (int im = 0; im < 2; ++im) {
                const int row = wm * 32 + im * 16 + a_row;
                const int g   = ks * 2 + a_gh;
                const uint32_t o = row * 128 + ((g ^ (row & 7)) << 4);
                ldmatrix_x4(ah[im], sA + o);
                if (two_pass) ldmatrix_x4(al[im], sAl + o);
            }
            uint32_t bh[4][4];
#pragma unroll
            for (int bp = 0; bp < 4; ++bp) {
                const int row = wn * 64 + bp * 16 + b_nof;
                const int g   = ks * 2 + b_gh;
                const uint32_t o = row * 128 + ((g ^ (row & 7)) << 4);
                ldmatrix_x4(bh[bp], sB + o);
            }
#pragma unroll
            for (int im = 0; im < 2; ++im)
#pragma unroll
                for (int in = 0; in < 8; ++in) {
                    const uint32_t* Bh = &bh[in >> 1][(in & 1) * 2];
                    mma_f16(acc[im][in], ah[im], Bh);
                    if (two_pass) mma_f16(acc[im][in], al[im], Bh);
                }
        }
    };

    issue(0, 0);
    issue(1, 1);
    issue(2, 2);

    CP_WAIT(2); __syncthreads();
    compute(0);
    __syncthreads();
    issue(3, 0);

    CP_WAIT(2); __syncthreads();
    compute(1);

    CP_WAIT(1); __syncthreads();
    compute(2);

    CP_WAIT(0); __syncthreads();
    compute(0);

    // ---- epilogue: bx 0,1 -> g_S0 fp32; bx>=2 -> g_Shi fp16
    const int r  = lane >> 2;
    const int cc = (lane & 3) * 2;
#pragma unroll
    for (int im = 0; im < 2; ++im) {
        const int mr = m0 + wm * 32 + im * 16 + r;
#pragma unroll
        for (int in = 0; in < 8; ++in) {
            const int ncol = wn * 64 + in * 8 + cc;
            const float2 bv = __ldg((const float2*)(bia + ncol));
            const float v00 = acc[im][in][0] + bv.x, v01 = acc[im][in][1] + bv.y;
            const float v10 = acc[im][in][2] + bv.x, v11 = acc[im][in][3] + bv.y;
            if (two_pass) {
                *(float2*)&g_S0[(size_t)mr * 256 + bx * 128 + ncol]       = make_float2(v00, v01);
                *(float2*)&g_S0[(size_t)(mr + 8) * 256 + bx * 128 + ncol] = make_float2(v10, v11);
            } else {
                const int c3 = (bx - 2) * 128 + ncol;                 // 0..767
                *(uint32_t*)&g_Shi[(size_t)mr * 768 + c3]       = h2u(__floats2half2_rn(v00, v01));
                *(uint32_t*)&g_Shi[(size_t)(mr + 8) * 768 + c3] = h2u(__floats2half2_rn(v10, v11));
            }
        }
    }
}

// ===========================================================================
// Kernel B: attention, fp16 single-pass both GEMMs, n-aware tile skipping.
// SMEM: ph1 Qhi[0,32K) Khi[32K,64K); ph3 Vhi[0,64K)
//       sscore fp32 [120][129] @65536; sP fp16 [128][128] @131072. Total 160K.
// ===========================================================================
#define AT_SCORES 65536
#define AT_SP     131072
#define AT_SMEM   163840

__global__ void __launch_bounds__(256, 1) attn_mma_kernel(float* __restrict__ out)
{
    extern __shared__ __align__(16) char smp[];
    const uint32_t sQhi = smem_u32(smp);
    const uint32_t sKhi = sQhi + 32768;
    const uint32_t sVhi = sQhi;            // phase3 alias [128 j][256 h] fp16
    float* sscore = (float*)(smp + AT_SCORES);
    const uint32_t sP = sQhi + AT_SP;

    const int seg = blockIdx.x;
    const int b   = blockIdx.y;
    const int n   = (seg == 0) ? 103 : (seg == 1) ? 119 : 11;
    const int off = (seg == 0) ? 0   : (seg == 1) ? 103 : 222;
    const size_t grow0 = (size_t)b * SEQ + off;
    const int nks16 = ((n + 15) >> 4) << 4;      // 112 / 128 / 16
    const int nkt   = nks16 >> 4;

    const int tid  = threadIdx.x;
    const int wid  = tid >> 5;
    const int lane = tid & 31;
    const int wm   = wid & 3;
    const int wn   = wid >> 2;

    const int a_row = lane & 15;
    const int a_gh  = lane >> 4;
    const int b_nof = (lane & 7) + ((lane & 16) ? 8 : 0);
    const int b_gh  = (lane >> 3) & 1;

    const bool act_a[2] = { (wm * 32)      < nks16,
                            (wm * 32 + 16) < nks16 };
    bool act_b[4];
#pragma unroll
    for (int bp = 0; bp < 4; ++bp) act_b[bp] = (wn * 64 + bp * 16) < nks16;

    float acc[2][8][4];
#pragma unroll
    for (int i = 0; i < 2; ++i)
#pragma unroll
        for (int j = 0; j < 8; ++j)
#pragma unroll
            for (int q = 0; q < 4; ++q) acc[i][j][q] = 0.0f;

    // ============ phase 1: scores = s1hi . s2hi^T (1-pass), 2 K-chunks
#pragma unroll 1
    for (int kc = 0; kc < 2; ++kc) {
        if (kc) __syncthreads();
#pragma unroll
        for (int it = 0; it < 8; ++it) {
            const int gi = tid + it * 256;
            const int row = gi >> 4, g = gi & 15;
            uint4 vh = make_uint4(0,0,0,0);
            if (row < n)
                vh = *(const uint4*)&g_Shi[(grow0 + row) * 768 + kc * 128 + g * 8];
            *(uint4*)(smp + row * 256 + ((g ^ (row & 7)) << 4)) = vh;
        }
#pragma unroll
        for (int it = 0; it < 8; ++it) {
            const int gi = tid + it * 256;
            const int row = gi >> 4, g = gi & 15;
            uint4 vh = make_uint4(0,0,0,0);
            if (row < n)
                vh = *(const uint4*)&g_Shi[(grow0 + row) * 768 + 256 + kc * 128 + g * 8];
            *(uint4*)(smp + 32768 + row * 256 + ((g ^ (row & 7)) << 4)) = vh;
        }
        __syncthreads();

#pragma unroll
        for (int ks = 0; ks < 8; ++ks) {
            uint32_t ah[2][4];
#pragma unroll
            for (int im = 0; im < 2; ++im) {
                if (!act_a[im]) continue;
                const int row = wm * 32 + im * 16 + a_row;
                const int g   = ks * 2 + a_gh;
                ldmatrix_x4(ah[im], sQhi + row * 256 + ((g ^ (row & 7)) << 4));
            }
            uint32_t bh[4][4];
#pragma unroll
            for (int bp = 0; bp < 4; ++bp) {
                if (!act_b[bp]) continue;
                const int row = wn * 64 + bp * 16 + b_nof;
                const int g   = ks * 2 + b_gh;
                ldmatrix_x4(bh[bp], sKhi + row * 256 + ((g ^ (row & 7)) << 4));
            }
#pragma unroll
            for (int im = 0; im < 2; ++im)
#pragma unroll
                for (int in = 0; in < 8; ++in) {
                    if (!act_a[im] || !act_b[in >> 1]) continue;
                    mma_f16(acc[im][in], ah[im], &bh[in >> 1][(in & 1) * 2]);
                }
        }
        __syncthreads();
    }

    // ============ phase 2: scale + mask -> sscore -> softmax -> sP fp16
    {
        const int r  = lane >> 2;
        const int cc = (lane & 3) * 2;
#pragma unroll
        for (int im = 0; im < 2; ++im) {
            const int g1 = wm * 32 + im * 16 + r;
            const int g2 = g1 + 8;
#pragma unroll
            for (int in = 0; in < 8; ++in) {
                if (!act_b[in >> 1]) continue;
                const int col = wn * 64 + in * 8 + cc;
                if (g1 < n) {
                    float vx = (col     >= n) ? NEG : acc[im][in][0] * SCALE + ((col     == g1) ? NEG : 0.f);
                    float vy = (col + 1 >= n) ? NEG : acc[im][in][1] * SCALE + ((col + 1 == g1) ? NEG : 0.f);
                    sscore[g1 * 129 + col]     = vx;
                    sscore[g1 * 129 + col + 1] = vy;
                }
                if (g2 < n) {
                    float vx = (col     >= n) ? NEG : acc[im][in][2] * SCALE + ((col     == g2) ? NEG : 0.f);
                    float vy = (col + 1 >= n) ? NEG : acc[im][in][3] * SCALE + ((col + 1 == g2) ? NEG : 0.f);
                    sscore[g2 * 129 + col]     = vx;
                    sscore[g2 * 129 + col + 1] = vy;
                }
            }
        }
    }
    __syncthreads();

    // softmax: 8 warps x 16 rows, over nks16 cols
#pragma unroll 1
    for (int rr = 0; rr < 16; ++rr) {
        const int gi = rr * 8 + wid;
        if (gi < n) {
            float* rowp = &sscore[gi * 129];
            float mx = -1e30f;
            for (int j = lane; j < nks16; j += 32) mx = fmaxf(mx, rowp[j]);
#pragma unroll
            for (int o = 16; o; o >>= 1) mx = fmaxf(mx, __shfl_xor_sync(0xffffffffu, mx, o));
            float ssum = 0.f;
            for (int j = lane; j < nks16; j += 32) {
                const float e = __expf(rowp[j] - mx);
                rowp[j] = e;
                ssum += e;
            }
#pragma unroll
            for (int o = 16; o; o >>= 1) ssum += __shfl_xor_sync(0xffffffffu, ssum, o);
            const float inv = 1.0f / ssum;
            for (int j = lane; j < nks16; j += 32) rowp[j] *= inv;
        }
    }
    __syncthreads();

    // ============ load V hi (s3) + convert probs -> sP fp16
#pragma unroll
    for (int it = 0; it < 16; ++it) {
        const int gi = tid + it * 256;
        const int j = gi >> 5, gg = gi & 31;
        uint4 vh = make_uint4(0,0,0,0);
        if (j < n) vh = *(const uint4*)&g_Shi[(grow0 + j) * 768 + 512 + gg * 8];
        *(uint4*)(smp + j * 512 + ((gg ^ (j & 7)) << 4)) = vh;
    }
#pragma unroll
    for (int it = 0; it < 8; ++it) {
        const int gi = tid + it * 256;
        const int row = gi >> 4, g = gi & 15;
        uint4 v = make_uint4(0, 0, 0, 0);
        if (row < n && g * 8 < nks16) {
            const float* rp = &sscore[row * 129 + g * 8];
            v.x = h2u(__floats2half2_rn(rp[0], rp[1]));
            v.y = h2u(__floats2half2_rn(rp[2], rp[3]));
            v.z = h2u(__floats2half2_rn(rp[4], rp[5]));
            v.w = h2u(__floats2half2_rn(rp[6], rp[7]));
        }
        *(uint4*)(smp + AT_SP + row * 256 + ((g ^ (row & 7)) << 4)) = v;
    }
    __syncthreads();

    // ============ phase 3: out = s0 - probs @ s3hi (1-pass), two halves
#pragma unroll 1
    for (int hb = 0; hb < 2; ++hb) {
        float acc2[2][8][4];
#pragma unroll
        for (int i = 0; i < 2; ++i)
#pragma unroll
            for (int j = 0; j < 8; ++j)
#pragma unroll
                for (int q = 0; q < 4; ++q) acc2[i][j][q] = 0.0f;

#pragma unroll 1
        for (int ks = 0; ks < nkt; ++ks) {
            uint32_t ap[2][4];
#pragma unroll
            for (int im = 0; im < 2; ++im) {
                if (!act_a[im]) continue;
                const int row = wm * 32 + im * 16 + a_row;
                const int g   = ks * 2 + a_gh;
                ldmatrix_x4(ap[im], sP + row * 256 + ((g ^ (row & 7)) << 4));
            }
            uint32_t bvh[4][4];
#pragma unroll
            for (int bp = 0; bp < 4; ++bp) {
                const int jrow = ks * 16 + (lane & 15);
                const int gg   = hb * 16 + wn * 8 + bp * 2 + (lane >> 4);
                ldmatrix_x4_t(bvh[bp], sVhi + jrow * 512 + ((gg ^ (jrow & 7)) << 4));
            }
#pragma unroll
            for (int im = 0; im < 2; ++im) {
                if (!act_a[im]) continue;
#pragma unroll
                for (int in = 0; in < 8; ++in)
                    mma_f16(acc2[im][in], ap[im], &bvh[in >> 1][(in & 1) * 2]);
            }
        }

        const int r  = lane >> 2;
        const int cc = (lane & 3) * 2;
#pragma unroll
        for (int im = 0; im < 2; ++im) {
            const int g1 = wm * 32 + im * 16 + r;
#pragma unroll
            for (int in = 0; in < 8; ++in) {
                const int h = hb * 128 + wn * 64 + in * 8 + cc;
                if (g1 < n) {
                    const float2 s0 = __ldg((const float2*)&g_S0[(grow0 + g1) * 256 + h]);
                    *(float2*)&out[(grow0 + g1) * 256 + h] =
                        make_float2(s0.x - acc2[im][in][0], s0.y - acc2[im][in][1]);
                }
                const int g2 = g1 + 8;
                if (g2 < n) {
                    const float2 s0 = __ldg((const float2*)&g_S0[(grow0 + g2) * 256 + h]);
                    *(float2*)&out[(grow0 + g2) * 256 + h] =
                        make_float2(s0.x - acc2[im][in][2], s0.y - acc2[im][in][3]);
                }
            }
        }
    }
}

// ---------------------------------------------------------------------------
extern "C" void kernel_launch(void* const* d_in, const int* in_sizes, int n_in,
                              void* d_out, int out_size)
{
    const float* toks = (const float*)d_in[0];
    const float* W0   = (const float*)d_in[1];
    const float* b0   = (const float*)d_in[2];
    const float* W1   = (const float*)d_in[3];
    const float* b1   = (const float*)d_in[4];
    const float* W2   = (const float*)d_in[5];
    const float* b2   = (const float*)d_in[6];
    const float* W3   = (const float*)d_in[7];
    const float* b3   = (const float*)d_in[8];
    float* out = (float*)d_out;

    __half *xhi, *xlo, *whi;
    cudaGetSymbolAddress((void**)&xhi, g_Xhi);
    cudaGetSymbolAddress((void**)&xlo, g_Xlo);
    cudaGetSymbolAddress((void**)&whi, g_Whi);

    const size_t x8 = (size_t)MROWS * 256 / 8;
    cvt_kernel<<<(unsigned)((x8 + 255) / 256), 256>>>(toks, xhi, xlo, x8);
    const size_t w8 = 256 * 256 / 8;
    cvt_hi_kernel<<<32, 256>>>(W0, whi,             w8);
    cvt_hi_kernel<<<32, 256>>>(W1, whi + 256 * 256, w8);
    cvt_hi_kernel<<<32, 256>>>(W2, whi + 512 * 256, w8);
    cvt_hi_kernel<<<32, 256>>>(W3, whi + 768 * 256, w8);

    cudaFuncSetAttribute(proj_mma_kernel,
                         cudaFuncAttributeMaxDynamicSharedMemorySize, PJ_SMEM);
    dim3 gA(8, MROWS / 128);
    proj_mma_kernel<<<gA, 256, PJ_SMEM>>>(b0, b1, b2, b3);

    cudaFuncSetAttribute(attn_mma_kernel,
                         cudaFuncAttributeMaxDynamicSharedMemorySize, AT_SMEM);
    dim3 gB(3, BATCH);
    attn_mma_kernel<<<gB, 256, AT_SMEM>>>(out);
}

// round 10
// speedup vs baseline: 4.9352x; 1.5330x over previous
#include <cuda_runtime.h>
#include <cuda_fp16.h>
#include <cstdint>
#include <math.h>

#define HIDDEN 256
#define SEQ    233
#define BATCH  1024
#define MROWS  (BATCH * SEQ)          // 238592 = 128 * 1864
#define SCALE  0.0625f                // 1/sqrt(256)
#define NEG    (-10000.0f)

// Scratch buffers (fp16 single-pass path)
static __device__ float   g_S0 [(size_t)MROWS * 256];   // s0 fp32
static __device__ __half  g_Shi[(size_t)MROWS * 768];   // s1|s2|s3 fp16
static __device__ __half  g_Xhi[(size_t)MROWS * 256];
static __device__ __half  g_Whi[1024 * 256];

__device__ __forceinline__ uint32_t smem_u32(const void* p) {
    uint32_t a;
    asm("{ .reg .u64 t; cvta.to.shared.u64 t, %1; cvt.u32.u64 %0, t; }" : "=r"(a) : "l"(p));
    return a;
}
__device__ __forceinline__ uint32_t h2u(__half2 h) {
    return *reinterpret_cast<uint32_t*>(&h);
}
__device__ __forceinline__ void ldmatrix_x4(uint32_t* r, uint32_t addr) {
    asm volatile("ldmatrix.sync.aligned.m8n8.x4.shared.b16 {%0,%1,%2,%3}, [%4];"
                 : "=r"(r[0]), "=r"(r[1]), "=r"(r[2]), "=r"(r[3]) : "r"(addr));
}
__device__ __forceinline__ void ldmatrix_x4_t(uint32_t* r, uint32_t addr) {
    asm volatile("ldmatrix.sync.aligned.m8n8.x4.trans.shared.b16 {%0,%1,%2,%3}, [%4];"
                 : "=r"(r[0]), "=r"(r[1]), "=r"(r[2]), "=r"(r[3]) : "r"(addr));
}
__device__ __forceinline__ void mma_f16(float* c, const uint32_t* a, const uint32_t* b) {
    asm volatile(
        "mma.sync.aligned.m16n8k16.row.col.f32.f16.f16.f32 "
        "{%0,%1,%2,%3}, {%4,%5,%6,%7}, {%8,%9}, {%0,%1,%2,%3};"
        : "+f"(c[0]), "+f"(c[1]), "+f"(c[2]), "+f"(c[3])
        : "r"(a[0]), "r"(a[1]), "r"(a[2]), "r"(a[3]), "r"(b[0]), "r"(b[1]));
}

#define CP_A16(dst, src) asm volatile("cp.async.cg.shared.global [%0], [%1], 16;" :: "r"(dst), "l"(src))
#define CP_COMMIT()      asm volatile("cp.async.commit_group;")
#define CP_WAIT(n)       asm volatile("cp.async.wait_group %0;" :: "n"(n))

// ===========================================================================
// Converter: fp32 -> fp16 (round-to-nearest), 8 elems / thread
// ===========================================================================
__global__ void __launch_bounds__(256) cvt_hi_kernel(
    const float* __restrict__ src, __half* __restrict__ hi, size_t n8)
{
    const size_t i = (size_t)blockIdx.x * blockDim.x + threadIdx.x;
    if (i < n8) {
        const float4 v0 = __ldg((const float4*)(src + i * 8));
        const float4 v1 = __ldg((const float4*)(src + i * 8 + 4));
        uint4 h;
        h.x = h2u(__floats2half2_rn(v0.x, v0.y));
        h.y = h2u(__floats2half2_rn(v0.z, v0.w));
        h.z = h2u(__floats2half2_rn(v1.x, v1.y));
        h.w = h2u(__floats2half2_rn(v1.z, v1.w));
        *(uint4*)(hi + i * 8) = h;
    }
}

// ===========================================================================
// Kernel A: proj, single-pass xhi·whi. cp.async 3-stage, BK=64.
// Stage (32KB): Ahi 16K | Bhi 16K.
// ===========================================================================
#define PJ_STAGE 32768
#define PJ_SMEM  (3 * PJ_STAGE)

__global__ void __launch_bounds__(256, 1) proj_mma_kernel(
    const float* __restrict__ B0, const float* __restrict__ B1,
    const float* __restrict__ B2, const float* __restrict__ B3)
{
    extern __shared__ __align__(16) char smp[];
    const uint32_t sbase = smem_u32(smp);

    const int tid  = threadIdx.x;
    const int wid  = tid >> 5;
    const int lane = tid & 31;
    const int wm   = wid & 3;
    const int wn   = wid >> 2;

    const int bx = blockIdx.x;         // 0..7 : 128-row slab of the 1024 outputs
    const int m0 = blockIdx.y * 128;
    const int wsel = bx >> 1;
    const float* bia = ((wsel == 0) ? B0 : (wsel == 1) ? B1 : (wsel == 2) ? B2 : B3)
                       + (bx & 1) * 128;

    float acc[2][8][4];
#pragma unroll
    for (int i = 0; i < 2; ++i)
#pragma unroll
        for (int j = 0; j < 8; ++j)
#pragma unroll
            for (int q = 0; q < 4; ++q) acc[i][j][q] = 0.0f;

    const int a_row = lane & 15;
    const int a_gh  = lane >> 4;
    const int b_nof = (lane & 7) + ((lane & 16) ? 8 : 0);
    const int b_gh  = (lane >> 3) & 1;

    auto issue = [&](int c, int buf) {
        const uint32_t sb = sbase + buf * PJ_STAGE;
#pragma unroll
        for (int it = 0; it < 4; ++it) {
            const int gi  = tid + it * 256;       // 0..1023
            const int row = gi >> 3;
            const int g   = gi & 7;
            const uint32_t o = row * 128 + ((g ^ (row & 7)) << 4);
            const size_t ax  = (size_t)(m0 + row) * 256 + c * 64 + g * 8;
            const size_t bxo = (size_t)(bx * 128 + row) * 256 + c * 64 + g * 8;
            CP_A16(sb + o,         (const char*)(g_Xhi + ax));
            CP_A16(sb + 16384 + o, (const char*)(g_Whi + bxo));
        }
        CP_COMMIT();
    };

    auto compute = [&](int buf) {
        const uint32_t sA = sbase + buf * PJ_STAGE;
        const uint32_t sB = sA + 16384;
#pragma unroll
        for (int ks = 0; ks < 4; ++ks) {
            uint32_t ah[2][4];
#pragma unroll
            for (int im = 0; im < 2; ++im) {
                const int row = wm * 32 + im * 16 + a_row;
                const int g   = ks * 2 + a_gh;
                ldmatrix_x4(ah[im], sA + row * 128 + ((g ^ (row & 7)) << 4));
            }
            uint32_t bh[4][4];
#pragma unroll
            for (int bp = 0; bp < 4; ++bp) {
                const int row = wn * 64 + bp * 16 + b_nof;
                const int g   = ks * 2 + b_gh;
                ldmatrix_x4(bh[bp], sB + row * 128 + ((g ^ (row & 7)) << 4));
            }
#pragma unroll
            for (int im = 0; im < 2; ++im)
#pragma unroll
                for (int in = 0; in < 8; ++in)
                    mma_f16(acc[im][in], ah[im], &bh[in >> 1][(in & 1) * 2]);
        }
    };

    issue(0, 0);
    issue(1, 1);
    issue(2, 2);

    CP_WAIT(2); __syncthreads();
    compute(0);
    __syncthreads();
    issue(3, 0);

    CP_WAIT(2); __syncthreads();
    compute(1);

    CP_WAIT(1); __syncthreads();
    compute(2);

    CP_WAIT(0); __syncthreads();
    compute(0);

    // ---- epilogue: bx 0,1 -> g_S0 fp32; bx>=2 -> g_Shi fp16
    const int r  = lane >> 2;
    const int cc = (lane & 3) * 2;
#pragma unroll
    for (int im = 0; im < 2; ++im) {
        const int mr = m0 + wm * 32 + im * 16 + r;
#pragma unroll
        for (int in = 0; in < 8; ++in) {
            const int ncol = wn * 64 + in * 8 + cc;
            const float2 bv = __ldg((const float2*)(bia + ncol));
            const float v00 = acc[im][in][0] + bv.x, v01 = acc[im][in][1] + bv.y;
            const float v10 = acc[im][in][2] + bv.x, v11 = acc[im][in][3] + bv.y;
            if (bx < 2) {
                *(float2*)&g_S0[(size_t)mr * 256 + bx * 128 + ncol]       = make_float2(v00, v01);
                *(float2*)&g_S0[(size_t)(mr + 8) * 256 + bx * 128 + ncol] = make_float2(v10, v11);
            } else {
                const int c3 = (bx - 2) * 128 + ncol;                 // 0..767
                *(uint32_t*)&g_Shi[(size_t)mr * 768 + c3]       = h2u(__floats2half2_rn(v00, v01));
                *(uint32_t*)&g_Shi[(size_t)(mr + 8) * 768 + c3] = h2u(__floats2half2_rn(v10, v11));
            }
        }
    }
}

// ===========================================================================
// Kernel B: attention, segment-packed (2 CTAs/batch), fp16 single-pass.
//   seg 0: law(103) + term(11) packed, n=114, cross-block masked
//   seg 1: accu(119), n=119
// SMEM (96KB, 2 CTAs/SM): ph1 Qhi[0,32K) Khi[32K,64K);
//   sscore fp32 [120][129] aliases [0,62K); V [0,64K) in ph3; sP @64K..96K.
// ===========================================================================
#define AT_SP   65536
#define AT_SMEM 98304

__global__ void __launch_bounds__(256, 2) attn_mma_kernel(float* __restrict__ out)
{
    extern __shared__ __align__(16) char smp[];
    const uint32_t sQhi = smem_u32(smp);
    const uint32_t sKhi = sQhi + 32768;
    const uint32_t sVhi = sQhi;            // phase3 alias [128 j][256 h] fp16
    float* sscore = (float*)smp;           // [120][129] fp32 aliases Q/K
    const uint32_t sP = sQhi + AT_SP;

    const int seg = blockIdx.x;            // 0: law+term, 1: accu
    const int b   = blockIdx.y;
    const int n   = seg ? 119 : 114;
    const size_t base = (size_t)b * SEQ;

    const int tid  = threadIdx.x;
    const int wid  = tid >> 5;
    const int lane = tid & 31;
    const int wm   = wid & 3;
    const int wn   = wid >> 2;

    const int a_row = lane & 15;
    const int a_gh  = lane >> 4;
    const int b_nof = (lane & 7) + ((lane & 16) ? 8 : 0);
    const int b_gh  = (lane >> 3) & 1;

    // packed row -> token index within the batch
    auto tok = [&](int r) -> int {
        return seg ? (103 + r) : (r < 103 ? r : r + 119);
    };

    float acc[2][8][4];
#pragma unroll
    for (int i = 0; i < 2; ++i)
#pragma unroll
        for (int j = 0; j < 8; ++j)
#pragma unroll
            for (int q = 0; q < 4; ++q) acc[i][j][q] = 0.0f;

    // ============ phase 1: scores = s1hi . s2hi^T, 2 K-chunks
#pragma unroll 1
    for (int kc = 0; kc < 2; ++kc) {
        if (kc) __syncthreads();
#pragma unroll
        for (int it = 0; it < 8; ++it) {
            const int gi = tid + it * 256;
            const int row = gi >> 4, g = gi & 15;
            uint4 vh = make_uint4(0,0,0,0);
            if (row < n)
                vh = *(const uint4*)&g_Shi[(base + tok(row)) * 768 + kc * 128 + g * 8];
            *(uint4*)(smp + row * 256 + ((g ^ (row & 7)) << 4)) = vh;
        }
#pragma unroll
        for (int it = 0; it < 8; ++it) {
            const int gi = tid + it * 256;
            const int row = gi >> 4, g = gi & 15;
            uint4 vh = make_uint4(0,0,0,0);
            if (row < n)
                vh = *(const uint4*)&g_Shi[(base + tok(row)) * 768 + 256 + kc * 128 + g * 8];
            *(uint4*)(smp + 32768 + row * 256 + ((g ^ (row & 7)) << 4)) = vh;
        }
        __syncthreads();

#pragma unroll
        for (int ks = 0; ks < 8; ++ks) {
            uint32_t ah[2][4];
#pragma unroll
            for (int im = 0; im < 2; ++im) {
                const int row = wm * 32 + im * 16 + a_row;
                const int g   = ks * 2 + a_gh;
                ldmatrix_x4(ah[im], sQhi + row * 256 + ((g ^ (row & 7)) << 4));
            }
            uint32_t bh[4][4];
#pragma unroll
            for (int bp = 0; bp < 4; ++bp) {
                const int row = wn * 64 + bp * 16 + b_nof;
                const int g   = ks * 2 + b_gh;
                ldmatrix_x4(bh[bp], sKhi + row * 256 + ((g ^ (row & 7)) << 4));
            }
#pragma unroll
            for (int im = 0; im < 2; ++im)
#pragma unroll
                for (int in = 0; in < 8; ++in)
                    mma_f16(acc[im][in], ah[im], &bh[in >> 1][(in & 1) * 2]);
        }
        __syncthreads();
    }

    // ============ phase 2: scale + masks -> sscore
    {
        const int r  = lane >> 2;
        const int cc = (lane & 3) * 2;
#pragma unroll
        for (int im = 0; im < 2; ++im) {
            const int g1 = wm * 32 + im * 16 + r;
            const int g2 = g1 + 8;
#pragma unroll
            for (int in = 0; in < 8; ++in) {
                const int col = wn * 64 + in * 8 + cc;
                const bool cb0 = (col < 103), cb1 = (col + 1 < 103);
                if (g1 < n) {
                    const bool rb = (g1 < 103) && (seg == 0);
                    const bool rB = (g1 < 103);
                    float m0v = (col     >= n || col     == g1 || (seg == 0 && (rB != cb0))) ? NEG : 0.f;
                    float m1v = (col + 1 >= n || col + 1 == g1 || (seg == 0 && (rB != cb1))) ? NEG : 0.f;
                    (void)rb;
                    sscore[g1 * 129 + col]     = acc[im][in][0] * SCALE + m0v;
                    sscore[g1 * 129 + col + 1] = acc[im][in][1] * SCALE + m1v;
                }
                if (g2 < n) {
                    const bool rB = (g2 < 103);
                    float m0v = (col     >= n || col     == g2 || (seg == 0 && (rB != cb0))) ? NEG : 0.f;
                    float m1v = (col + 1 >= n || col + 1 == g2 || (seg == 0 && (rB != cb1))) ? NEG : 0.f;
                    sscore[g2 * 129 + col]     = acc[im][in][2] * SCALE + m0v;
                    sscore[g2 * 129 + col + 1] = acc[im][in][3] * SCALE + m1v;
                }
            }
        }
    }
    __syncthreads();

    // ============ softmax: 8 warps x 15 rows (covers n<=119), 128 cols
#pragma unroll 1
    for (int rr = 0; rr < 15; ++rr) {
        const int gi = rr * 8 + wid;
        if (gi < n) {
            float* rowp = &sscore[gi * 129];
            float mx = -1e30f;
#pragma unroll
            for (int j = 0; j < 4; ++j) mx = fmaxf(mx, rowp[lane + j * 32]);
#pragma unroll
            for (int o = 16; o; o >>= 1) mx = fmaxf(mx, __shfl_xor_sync(0xffffffffu, mx, o));
            float ssum = 0.f;
            float ev[4];
#pragma unroll
            for (int j = 0; j < 4; ++j) {
                ev[j] = __expf(rowp[lane + j * 32] - mx);
                ssum += ev[j];
            }
#pragma unroll
            for (int o = 16; o; o >>= 1) ssum += __shfl_xor_sync(0xffffffffu, ssum, o);
            const float inv = 1.0f / ssum;
#pragma unroll
            for (int j = 0; j < 4; ++j) rowp[lane + j * 32] = ev[j] * inv;
        }
    }
    __syncthreads();

    // ============ convert probs -> sP fp16 (before V overwrites sscore)
#pragma unroll
    for (int it = 0; it < 8; ++it) {
        const int gi = tid + it * 256;
        const int row = gi >> 4, g = gi & 15;
        uint4 v = make_uint4(0, 0, 0, 0);
        if (row < n) {
            const float* rp = &sscore[row * 129 + g * 8];
            v.x = h2u(__floats2half2_rn(rp[0], rp[1]));
            v.y = h2u(__floats2half2_rn(rp[2], rp[3]));
            v.z = h2u(__floats2half2_rn(rp[4], rp[5]));
            v.w = h2u(__floats2half2_rn(rp[6], rp[7]));
        }
        *(uint4*)(smp + AT_SP + row * 256 + ((g ^ (row & 7)) << 4)) = v;
    }
    __syncthreads();

    // ============ load V hi (s3) over the dead sscore region
#pragma unroll
    for (int it = 0; it < 16; ++it) {
        const int gi = tid + it * 256;
        const int j = gi >> 5, gg = gi & 31;
        uint4 vh = make_uint4(0,0,0,0);
        if (j < n) vh = *(const uint4*)&g_Shi[(base + tok(j)) * 768 + 512 + gg * 8];
        *(uint4*)(smp + j * 512 + ((gg ^ (j & 7)) << 4)) = vh;
    }
    __syncthreads();

    // ============ phase 3: out = s0 - probs @ s3hi, two 128-col halves
#pragma unroll 1
    for (int hb = 0; hb < 2; ++hb) {
        float acc2[2][8][4];
#pragma unroll
        for (int i = 0; i < 2; ++i)
#pragma unroll
            for (int j = 0; j < 8; ++j)
#pragma unroll
                for (int q = 0; q < 4; ++q) acc2[i][j][q] = 0.0f;

#pragma unroll
        for (int ks = 0; ks < 8; ++ks) {
            uint32_t ap[2][4];
#pragma unroll
            for (int im = 0; im < 2; ++im) {
                const int row = wm * 32 + im * 16 + a_row;
                const int g   = ks * 2 + a_gh;
                ldmatrix_x4(ap[im], sP + row * 256 + ((g ^ (row & 7)) << 4));
            }
            uint32_t bvh[4][4];
#pragma unroll
            for (int bp = 0; bp < 4; ++bp) {
                const int jrow = ks * 16 + (lane & 15);
                const int gg   = hb * 16 + wn * 8 + bp * 2 + (lane >> 4);
                ldmatrix_x4_t(bvh[bp], sVhi + jrow * 512 + ((gg ^ (jrow & 7)) << 4));
            }
#pragma unroll
            for (int im = 0; im < 2; ++im)
#pragma unroll
                for (int in = 0; in < 8; ++in)
                    mma_f16(acc2[im][in], ap[im], &bvh[in >> 1][(in & 1) * 2]);
        }

        const int r  = lane >> 2;
        const int cc = (lane & 3) * 2;
#pragma unroll
        for (int im = 0; im < 2; ++im) {
            const int g1 = wm * 32 + im * 16 + r;
#pragma unroll
            for (int in = 0; in < 8; ++in) {
                const int h = hb * 128 + wn * 64 + in * 8 + cc;
                if (g1 < n) {
                    const size_t grow = base + tok(g1);
                    const float2 s0 = __ldg((const float2*)&g_S0[grow * 256 + h]);
                    *(float2*)&out[grow * 256 + h] =
                        make_float2(s0.x - acc2[im][in][0], s0.y - acc2[im][in][1]);
                }
                const int g2 = g1 + 8;
                if (g2 < n) {
                    const size_t grow = base + tok(g2);
                    const float2 s0 = __ldg((const float2*)&g_S0[grow * 256 + h]);
                    *(float2*)&out[grow * 256 + h] =
                        make_float2(s0.x - acc2[im][in][2], s0.y - acc2[im][in][3]);
                }
            }
        }
    }
}

// ---------------------------------------------------------------------------
extern "C" void kernel_launch(void* const* d_in, const int* in_sizes, int n_in,
                              void* d_out, int out_size)
{
    const float* toks = (const float*)d_in[0];
    const float* W0   = (const float*)d_in[1];
    const float* b0   = (const float*)d_in[2];
    const float* W1   = (const float*)d_in[3];
    const float* b1   = (const float*)d_in[4];
    const float* W2   = (const float*)d_in[5];
    const float* b2   = (const float*)d_in[6];
    const float* W3   = (const float*)d_in[7];
    const float* b3   = (const float*)d_in[8];
    float* out = (float*)d_out;

    __half *xhi, *whi;
    cudaGetSymbolAddress((void**)&xhi, g_Xhi);
    cudaGetSymbolAddress((void**)&whi, g_Whi);

    const size_t x8 = (size_t)MROWS * 256 / 8;
    cvt_hi_kernel<<<(unsigned)((x8 + 255) / 256), 256>>>(toks, xhi, x8);
    const size_t w8 = 256 * 256 / 8;
    cvt_hi_kernel<<<32, 256>>>(W0, whi,             w8);
    cvt_hi_kernel<<<32, 256>>>(W1, whi + 256 * 256, w8);
    cvt_hi_kernel<<<32, 256>>>(W2, whi + 512 * 256, w8);
    cvt_hi_kernel<<<32, 256>>>(W3, whi + 768 * 256, w8);

    cudaFuncSetAttribute(proj_mma_kernel,
                         cudaFuncAttributeMaxDynamicSharedMemorySize, PJ_SMEM);
    dim3 gA(8, MROWS / 128);
    proj_mma_kernel<<<gA, 256, PJ_SMEM>>>(b0, b1, b2, b3);

    cudaFuncSetAttribute(attn_mma_kernel,
                         cudaFuncAttributeMaxDynamicSharedMemorySize, AT_SMEM);
    dim3 gB(2, BATCH);
    attn_mma_kernel<<<gB, 256, AT_SMEM>>>(out);
}